// round 7
// baseline (speedup 1.0000x reference)
#include <cuda_runtime.h>
#include <math.h>
#include <stdint.h>

#define T_LEN   49152
#define H       128
#define NCLS    256
#define OW      16386
#define SKIP_OFF 32766      /* T_LEN - OW */
#define TT      128
#define KC      32
#define NLAYERS 28

#define RES_SZ  (4*H*T_LEN)     /* 25,165,824 */
#define SKIP_SZ (4*H*OW)        /* 8,389,632  */

#define PK_LAYER  81920
#define PK_LAYERS (27*PK_LAYER)         /* 2,211,840 */
#define PK_W10T   (PK_LAYERS)
#define PK_W11T   (PK_W10T + 16384)
#define PK_W12T   (PK_W11T + 16384)
#define PK_WHCT   (PK_W12T + 16384)
#define PK_TOTAL  (PK_WHCT + 65536)     /* 2,326,528 */

__device__ __align__(16) float  g_resbuf[2][RES_SZ];
__device__ __align__(16) float  g_skip[SKIP_SZ];
__device__ __align__(16) float  g_y2[SKIP_SZ];
__device__ __align__(16) float  g_wpack[PK_TOTAL];
__device__ double g_stats[NLAYERS*256];
__device__ float  g_bns[NLAYERS*H];
__device__ float  g_bnt[NLAYERS*H];

/* ---------------- f32x2 packed-FMA helpers (Blackwell) ------------- */
__device__ __forceinline__ void ffma2(unsigned long long &acc,
                                      unsigned long long x,
                                      unsigned long long w) {
    asm("fma.rn.f32x2 %0, %1, %2, %0;" : "+l"(acc) : "l"(x), "l"(w));
}
__device__ __forceinline__ unsigned long long pack2(float lo, float hi) {
    unsigned long long r;
    asm("mov.b64 %0, {%1, %2};" : "=l"(r) : "f"(lo), "f"(hi));
    return r;
}
__device__ __forceinline__ float2 unpack2(unsigned long long v) {
    float lo, hi;
    asm("mov.b64 {%0, %1}, %2;" : "=f"(lo), "=f"(hi) : "l"(v));
    return make_float2(lo, hi);
}
__device__ __forceinline__ float sigm(float z) { return 1.f / (1.f + expf(-z)); }

/* ------------------------------------------------------------------ */
/* Weight repack: Wcat[k][m] (k-major) per layer + transposed 1x1s    */
/* ------------------------------------------------------------------ */
__global__ void pack_kernel(const float* __restrict__ Wf, const float* __restrict__ Wg,
                            const float* __restrict__ W1, const float* __restrict__ W10,
                            const float* __restrict__ W11, const float* __restrict__ W12,
                            const float* __restrict__ Whc)
{
    int idx = blockIdx.x * blockDim.x + threadIdx.x;
    if (idx >= PK_TOTAL) return;
    float v;
    if (idx < PK_LAYERS) {
        int j = idx / PK_LAYER;
        int r = idx - j * PK_LAYER;
        if (r < 65536) {
            int k = r >> 8, m = r & 255;
            int tap = k >> 7, c = k & 127;
            if (m < 128) v = Wf[((j*128 + m)*128 + c)*2 + tap];
            else         v = Wg[((j*128 + (m-128))*128 + c)*2 + tap];
        } else {
            int rr = r - 65536;
            int c = rr >> 7, o = rr & 127;
            v = W1[(j*128 + o)*128 + c];
        }
    } else if (idx < PK_W11T) {
        int rr = idx - PK_W10T; int c = rr >> 7, o = rr & 127; v = W10[o*128 + c];
    } else if (idx < PK_W12T) {
        int rr = idx - PK_W11T; int c = rr >> 7, o = rr & 127; v = W11[o*128 + c];
    } else if (idx < PK_WHCT) {
        int rr = idx - PK_W12T; int c = rr >> 7, o = rr & 127; v = W12[o*128 + c];
    } else {
        int rr = idx - PK_WHCT;
        int k = rr >> 8, o = rr & 255;
        int tap = k >> 7, c = k & 127;
        v = Whc[(o*128 + c)*2 + tap];
    }
    g_wpack[idx] = v;
}

__global__ void zero_stats_kernel()
{
    int i = blockIdx.x * blockDim.x + threadIdx.x;
    if (i < NLAYERS*256) g_stats[i] = 0.0;
}

/* ------------------------------------------------------------------ */
__global__ void bn_finalize_kernel(const float* __restrict__ gamma,
                                   const float* __restrict__ beta, int layer)
{
    int c = threadIdx.x;               /* 128 threads */
    const double N = 4.0 * (double)T_LEN;
    double s = g_stats[layer*256 + c];
    double q = g_stats[layer*256 + 128 + c];
    double mean = s / N;
    double var  = q / N - mean*mean;
    float sc = gamma[layer*H + c] * rsqrtf((float)var + 1e-5f);
    g_bns[layer*H + c] = sc;
    g_bnt[layer*H + c] = fmaf(-(float)mean, sc, beta[layer*H + c]);
}

/* ------------------------------------------------------------------ */
/* stats helper: warp-reduce two (sum, sumsq) pairs, lane0 atomics    */
/* ------------------------------------------------------------------ */
__device__ __forceinline__ void stats_commit(int layer, int o0, int o1,
                                             float ls0, float lq0,
                                             float ls1, float lq1, int lane)
{
    #pragma unroll
    for (int off = 16; off; off >>= 1) {
        ls0 += __shfl_xor_sync(0xffffffffu, ls0, off);
        lq0 += __shfl_xor_sync(0xffffffffu, lq0, off);
        ls1 += __shfl_xor_sync(0xffffffffu, ls1, off);
        lq1 += __shfl_xor_sync(0xffffffffu, lq1, off);
    }
    if (lane == 0) {
        atomicAdd(&g_stats[layer*256 + o0],       (double)ls0);
        atomicAdd(&g_stats[layer*256 + 128 + o0], (double)lq0);
        atomicAdd(&g_stats[layer*256 + o1],       (double)ls1);
        atomicAdd(&g_stats[layer*256 + 128 + o1], (double)lq1);
    }
}

/* 1x1 GEMM inner chunk: 64 k-values from xs, pairs over out-channel   */
__device__ __forceinline__ void gemm1x1_chunk(const float* __restrict__ xsm,
                                              const float* __restrict__ wsm,
                                              unsigned long long acc[4][4],
                                              int cb, int lane, int og)
{
    #pragma unroll
    for (int cc = 0; cc < 64; cc++) {
        float4 xv = *(const float4*)(xsm + (cb+cc)*TT + lane*4);
        unsigned long long xp0 = pack2(xv.x, xv.x);
        unsigned long long xp1 = pack2(xv.y, xv.y);
        unsigned long long xp2 = pack2(xv.z, xv.z);
        unsigned long long xp3 = pack2(xv.w, xv.w);
        const ulonglong2* w2 = (const ulonglong2*)(wsm + cc*128 + og*8);
        ulonglong2 wA = w2[0], wB = w2[1];
        ffma2(acc[0][0], xp0, wA.x); ffma2(acc[0][1], xp1, wA.x);
        ffma2(acc[0][2], xp2, wA.x); ffma2(acc[0][3], xp3, wA.x);
        ffma2(acc[1][0], xp0, wA.y); ffma2(acc[1][1], xp1, wA.y);
        ffma2(acc[1][2], xp2, wA.y); ffma2(acc[1][3], xp3, wA.y);
        ffma2(acc[2][0], xp0, wB.x); ffma2(acc[2][1], xp1, wB.x);
        ffma2(acc[2][2], xp2, wB.x); ffma2(acc[2][3], xp3, wB.x);
        ffma2(acc[3][0], xp0, wB.y); ffma2(acc[3][1], xp1, wB.y);
        ffma2(acc[3][2], xp2, wB.y); ffma2(acc[3][3], xp3, wB.y);
    }
}

/* ------------------------------------------------------------------ */
/* Layer 0: in_channels = 1                                            */
/* ------------------------------------------------------------------ */
__global__ void __launch_bounds__(512,1) layer0_kernel(
    const float* __restrict__ x,  const float* __restrict__ Wf0,
    const float* __restrict__ bf0, const float* __restrict__ Wg0,
    const float* __restrict__ bg0, const float* __restrict__ b10)
{
    extern __shared__ float sm[];
    float* hs   = sm;                 /* 16384 */
    float* wsm  = sm + 16384;         /* 8192  */
    float* xs   = sm + 24576;         /* 132   */

    int b  = blockIdx.y;
    int t0 = blockIdx.x * TT;
    int tid = threadIdx.x, lane = tid & 31, og = tid >> 5;

    const float* xb = x + (size_t)b * T_LEN;
    if (tid < 129) {
        int t = t0 - 1 + tid;
        xs[tid] = (t >= 0) ? xb[t] : 0.f;
    }
    __syncthreads();

    /* gated conv, in_ch = 1, dilation 1 */
    #pragma unroll
    for (int i = 0; i < 8; i++) {
        int c = og*8 + i;
        float wfa = Wf0[c*2], wfb = Wf0[c*2+1];
        float wga = Wg0[c*2], wgb = Wg0[c*2+1];
        float bfv = bf0[c],   bgv = bg0[c];
        #pragma unroll
        for (int u = 0; u < 4; u++) {
            int tt = lane*4 + u;
            float xm = xs[tt], x0 = xs[tt+1];
            float zf = fmaf(wfa, xm, fmaf(wfb, x0, bfv));
            float zg = fmaf(wga, xm, fmaf(wgb, x0, bgv));
            hs[c*TT + tt] = tanhf(zf) * sigm(zg);
        }
    }
    __syncthreads();

    /* 1x1 conv */
    unsigned long long acc2[4][4];
    #pragma unroll
    for (int p = 0; p < 4; p++) {
        unsigned long long v = pack2(b10[og*8 + 2*p], b10[og*8 + 2*p + 1]);
        #pragma unroll
        for (int u = 0; u < 4; u++) acc2[p][u] = v;
    }
    const float* w1g = g_wpack + PK_W10T;
    for (int ch = 0; ch < 2; ch++) {
        #pragma unroll
        for (int r = 0; r < 4; r++) {
            int fidx = (r*512 + tid) * 4;
            *(float4*)(wsm + fidx) = *(const float4*)(w1g + ch*8192 + fidx);
        }
        __syncthreads();
        gemm1x1_chunk(hs, wsm, acc2, ch*64, lane, og);
        __syncthreads();
    }

    /* epilogue — NOTE: xs+1 is only 4B-aligned, so load the residual
       input with scalar LDS, never float4 (misaligned-address trap). */
    float* rout = g_resbuf[0] + (size_t)b * H * T_LEN;
    float* ssb  = g_skip + (size_t)b * H * OW;
    float xr0 = xs[1 + lane*4];
    float xr1 = xs[2 + lane*4];
    float xr2 = xs[3 + lane*4];
    float xr3 = xs[4 + lane*4];
    #pragma unroll
    for (int p = 0; p < 4; p++) {
        int o0 = og*8 + 2*p, o1 = o0 + 1;
        float2 s0 = unpack2(acc2[p][0]), s1 = unpack2(acc2[p][1]);
        float2 s2 = unpack2(acc2[p][2]), s3 = unpack2(acc2[p][3]);
        float4 rv0 = make_float4(s0.x+xr0, s1.x+xr1, s2.x+xr2, s3.x+xr3);
        float4 rv1 = make_float4(s0.y+xr0, s1.y+xr1, s2.y+xr2, s3.y+xr3);
        *(float4*)(rout + (size_t)o0*T_LEN + t0 + lane*4) = rv0;
        *(float4*)(rout + (size_t)o1*T_LEN + t0 + lane*4) = rv1;
        float ls0 = rv0.x+rv0.y+rv0.z+rv0.w;
        float lq0 = rv0.x*rv0.x+rv0.y*rv0.y+rv0.z*rv0.z+rv0.w*rv0.w;
        float ls1 = rv1.x+rv1.y+rv1.z+rv1.w;
        float lq1 = rv1.x*rv1.x+rv1.y*rv1.y+rv1.z*rv1.z+rv1.w*rv1.w;
        float sk0[4] = {s0.x, s1.x, s2.x, s3.x};
        float sk1[4] = {s0.y, s1.y, s2.y, s3.y};
        #pragma unroll
        for (int u = 0; u < 4; u++) {
            int t = t0 + lane*4 + u;
            if (t >= SKIP_OFF) {
                ssb[(size_t)o0*OW + (t - SKIP_OFF)] = sk0[u];
                ssb[(size_t)o1*OW + (t - SKIP_OFF)] = sk1[u];
            }
        }
        stats_commit(0, o0, o1, ls0, lq0, ls1, lq1, lane);
    }
}

/* ------------------------------------------------------------------ */
/* Fused layer kernel (layers 1..27)                                  */
/* ------------------------------------------------------------------ */
__global__ void __launch_bounds__(512,1) layer_kernel(
    const float* __restrict__ bfA, const float* __restrict__ bgA,
    const float* __restrict__ b1A, int layer, int d)
{
    extern __shared__ float sm[];
    float* tileA = sm;
    float* tileB = sm + H*TT;
    float* wsm   = sm + 2*H*TT;

    const float* resin  = g_resbuf[(layer-1) & 1];
    float*       resout = g_resbuf[layer & 1];

    int b  = blockIdx.y;
    int t0 = blockIdx.x * TT;
    int tid = threadIdx.x, lane = tid & 31, og = tid >> 5;

    const float* __restrict__ bns = g_bns + (layer-1)*H;
    const float* __restrict__ bnt = g_bnt + (layer-1)*H;
    const float* src = resin + (size_t)b * H * T_LEN;

    /* load normalized input tiles: tileB = x_norm(t), tileA = x_norm(t-d) */
    if ((d & 3) == 0) {
        #pragma unroll
        for (int r = 0; r < 8; r++) {
            int c = og + 16*r;
            float s = bns[c], tsh = bnt[c];
            const float* row = src + (size_t)c * T_LEN;
            float4 vB = *(const float4*)(row + t0 + lane*4);
            *(float4*)(tileB + c*TT + lane*4) =
                make_float4(fmaf(s,vB.x,tsh), fmaf(s,vB.y,tsh), fmaf(s,vB.z,tsh), fmaf(s,vB.w,tsh));
            int ta = t0 - d + lane*4;
            float4 oA = make_float4(0.f,0.f,0.f,0.f);
            if (ta >= 0) {
                float4 vA = *(const float4*)(row + ta);
                oA = make_float4(fmaf(s,vA.x,tsh), fmaf(s,vA.y,tsh), fmaf(s,vA.z,tsh), fmaf(s,vA.w,tsh));
            }
            *(float4*)(tileA + c*TT + lane*4) = oA;
        }
    } else {
        #pragma unroll
        for (int r = 0; r < 8; r++) {
            int c = og + 16*r;
            float s = bns[c], tsh = bnt[c];
            const float* row = src + (size_t)c * T_LEN;
            float4 vB = *(const float4*)(row + t0 + lane*4);
            *(float4*)(tileB + c*TT + lane*4) =
                make_float4(fmaf(s,vB.x,tsh), fmaf(s,vB.y,tsh), fmaf(s,vB.z,tsh), fmaf(s,vB.w,tsh));
            #pragma unroll
            for (int u = 0; u < 4; u++) {
                int ta = t0 - d + lane*4 + u;
                tileA[c*TT + lane*4 + u] = (ta >= 0) ? fmaf(s, row[ta], tsh) : 0.f;
            }
        }
    }
    __syncthreads();

    /* gated conv: M=256 (f||g), K=256 (tap0=tileA, tap1=tileB) */
    unsigned long long accf[4][4], accg[4][4];
    {
        const float* bfL = bfA + (layer-1)*H;
        const float* bgL = bgA + (layer-1)*H;
        #pragma unroll
        for (int p = 0; p < 4; p++) {
            unsigned long long vf = pack2(bfL[og*8+2*p], bfL[og*8+2*p+1]);
            unsigned long long vg = pack2(bgL[og*8+2*p], bgL[og*8+2*p+1]);
            #pragma unroll
            for (int u = 0; u < 4; u++) { accf[p][u] = vf; accg[p][u] = vg; }
        }
    }
    const float* wbase = g_wpack + (size_t)(layer-1) * PK_LAYER;
    for (int ch = 0; ch < 8; ch++) {
        const float* wgp = wbase + ch * (KC*256);
        #pragma unroll
        for (int r = 0; r < 4; r++) {
            int fidx = (r*512 + tid) * 4;
            *(float4*)(wsm + fidx) = *(const float4*)(wgp + fidx);
        }
        __syncthreads();
        const float* xsrc = ((ch < 4) ? tileA : tileB) + ((ch & 3) * KC) * TT;
        #pragma unroll
        for (int kk = 0; kk < KC; kk++) {
            float4 xv = *(const float4*)(xsrc + kk*TT + lane*4);
            unsigned long long xp0 = pack2(xv.x, xv.x);
            unsigned long long xp1 = pack2(xv.y, xv.y);
            unsigned long long xp2 = pack2(xv.z, xv.z);
            unsigned long long xp3 = pack2(xv.w, xv.w);
            const ulonglong2* wf2 = (const ulonglong2*)(wsm + kk*256 + og*8);
            const ulonglong2* wg2 = (const ulonglong2*)(wsm + kk*256 + 128 + og*8);
            ulonglong2 wfA = wf2[0], wfB = wf2[1];
            ulonglong2 wgA = wg2[0], wgB = wg2[1];
            ffma2(accf[0][0], xp0, wfA.x); ffma2(accf[0][1], xp1, wfA.x);
            ffma2(accf[0][2], xp2, wfA.x); ffma2(accf[0][3], xp3, wfA.x);
            ffma2(accf[1][0], xp0, wfA.y); ffma2(accf[1][1], xp1, wfA.y);
            ffma2(accf[1][2], xp2, wfA.y); ffma2(accf[1][3], xp3, wfA.y);
            ffma2(accf[2][0], xp0, wfB.x); ffma2(accf[2][1], xp1, wfB.x);
            ffma2(accf[2][2], xp2, wfB.x); ffma2(accf[2][3], xp3, wfB.x);
            ffma2(accf[3][0], xp0, wfB.y); ffma2(accf[3][1], xp1, wfB.y);
            ffma2(accf[3][2], xp2, wfB.y); ffma2(accf[3][3], xp3, wfB.y);
            ffma2(accg[0][0], xp0, wgA.x); ffma2(accg[0][1], xp1, wgA.x);
            ffma2(accg[0][2], xp2, wgA.x); ffma2(accg[0][3], xp3, wgA.x);
            ffma2(accg[1][0], xp0, wgA.y); ffma2(accg[1][1], xp1, wgA.y);
            ffma2(accg[1][2], xp2, wgA.y); ffma2(accg[1][3], xp3, wgA.y);
            ffma2(accg[2][0], xp0, wgB.x); ffma2(accg[2][1], xp1, wgB.x);
            ffma2(accg[2][2], xp2, wgB.x); ffma2(accg[2][3], xp3, wgB.x);
            ffma2(accg[3][0], xp0, wgB.y); ffma2(accg[3][1], xp1, wgB.y);
            ffma2(accg[3][2], xp2, wgB.y); ffma2(accg[3][3], xp3, wgB.y);
        }
        __syncthreads();
    }

    /* gating -> hs (reuse tileA); one STS.128 per channel */
    float* hs = tileA;
    #pragma unroll
    for (int p = 0; p < 4; p++) {
        float2 f0 = unpack2(accf[p][0]), f1 = unpack2(accf[p][1]);
        float2 f2 = unpack2(accf[p][2]), f3 = unpack2(accf[p][3]);
        float2 g0 = unpack2(accg[p][0]), g1 = unpack2(accg[p][1]);
        float2 g2 = unpack2(accg[p][2]), g3 = unpack2(accg[p][3]);
        float4 h0 = make_float4(tanhf(f0.x)*sigm(g0.x), tanhf(f1.x)*sigm(g1.x),
                                tanhf(f2.x)*sigm(g2.x), tanhf(f3.x)*sigm(g3.x));
        float4 h1 = make_float4(tanhf(f0.y)*sigm(g0.y), tanhf(f1.y)*sigm(g1.y),
                                tanhf(f2.y)*sigm(g2.y), tanhf(f3.y)*sigm(g3.y));
        *(float4*)(hs + (og*8+2*p)*TT + lane*4)   = h0;
        *(float4*)(hs + (og*8+2*p+1)*TT + lane*4) = h1;
    }
    __syncthreads();

    /* 1x1 conv */
    unsigned long long acc2[4][4];
    {
        const float* b1L = b1A + (layer-1)*H;
        #pragma unroll
        for (int p = 0; p < 4; p++) {
            unsigned long long v = pack2(b1L[og*8+2*p], b1L[og*8+2*p+1]);
            #pragma unroll
            for (int u = 0; u < 4; u++) acc2[p][u] = v;
        }
    }
    const float* w1g = wbase + 65536;
    for (int ch = 0; ch < 2; ch++) {
        #pragma unroll
        for (int r = 0; r < 4; r++) {
            int fidx = (r*512 + tid) * 4;
            *(float4*)(wsm + fidx) = *(const float4*)(w1g + ch*8192 + fidx);
        }
        __syncthreads();
        gemm1x1_chunk(hs, wsm, acc2, ch*64, lane, og);
        __syncthreads();
    }

    /* epilogue: residual, store, BN stats, skip accumulate */
    float* rout = resout + (size_t)b * H * T_LEN;
    float* ssb  = g_skip + (size_t)b * H * OW;
    #pragma unroll
    for (int p = 0; p < 4; p++) {
        int o0 = og*8 + 2*p, o1 = o0 + 1;
        float2 s0 = unpack2(acc2[p][0]), s1 = unpack2(acc2[p][1]);
        float2 s2 = unpack2(acc2[p][2]), s3 = unpack2(acc2[p][3]);
        float4 xB0 = *(const float4*)(tileB + o0*TT + lane*4);
        float4 xB1 = *(const float4*)(tileB + o1*TT + lane*4);
        float4 rv0 = make_float4(s0.x+xB0.x, s1.x+xB0.y, s2.x+xB0.z, s3.x+xB0.w);
        float4 rv1 = make_float4(s0.y+xB1.x, s1.y+xB1.y, s2.y+xB1.z, s3.y+xB1.w);
        *(float4*)(rout + (size_t)o0*T_LEN + t0 + lane*4) = rv0;
        *(float4*)(rout + (size_t)o1*T_LEN + t0 + lane*4) = rv1;
        float ls0 = rv0.x+rv0.y+rv0.z+rv0.w;
        float lq0 = rv0.x*rv0.x+rv0.y*rv0.y+rv0.z*rv0.z+rv0.w*rv0.w;
        float ls1 = rv1.x+rv1.y+rv1.z+rv1.w;
        float lq1 = rv1.x*rv1.x+rv1.y*rv1.y+rv1.z*rv1.z+rv1.w*rv1.w;
        float sk0[4] = {s0.x, s1.x, s2.x, s3.x};
        float sk1[4] = {s0.y, s1.y, s2.y, s3.y};
        #pragma unroll
        for (int u = 0; u < 4; u++) {
            int t = t0 + lane*4 + u;
            if (t >= SKIP_OFF) {
                ssb[(size_t)o0*OW + (t - SKIP_OFF)] += sk0[u];
                ssb[(size_t)o1*OW + (t - SKIP_OFF)] += sk1[u];
            }
        }
        stats_commit(layer, o0, o1, ls0, lq0, ls1, lq1, lane);
    }
}

/* ------------------------------------------------------------------ */
/* Head part 1: y2 = relu(W12 @ relu(W11 @ skip_sum + b11) + b12)     */
/* ------------------------------------------------------------------ */
__global__ void __launch_bounds__(512,1) head1_kernel(
    const float* __restrict__ b11, const float* __restrict__ b12)
{
    extern __shared__ float sm[];
    float* xs  = sm;
    float* ys  = sm + 16384;
    float* wsm = sm + 32768;

    int b  = blockIdx.y;
    int t0 = blockIdx.x * TT;
    int tid = threadIdx.x, lane = tid & 31, og = tid >> 5;

    const float* sk = g_skip + (size_t)b * H * OW;
    #pragma unroll
    for (int r = 0; r < 32; r++) {
        int id = r*512 + tid;
        int c = id >> 7, tt = id & 127;
        int t = t0 + tt;
        xs[c*TT + tt] = (t < OW) ? sk[(size_t)c*OW + t] : 0.f;
    }
    __syncthreads();

    unsigned long long acc[4][4];
    #pragma unroll
    for (int p = 0; p < 4; p++) {
        unsigned long long v = pack2(b11[og*8+2*p], b11[og*8+2*p+1]);
        #pragma unroll
        for (int u = 0; u < 4; u++) acc[p][u] = v;
    }
    for (int ch = 0; ch < 2; ch++) {
        #pragma unroll
        for (int r = 0; r < 4; r++) {
            int fidx = (r*512 + tid) * 4;
            *(float4*)(wsm + fidx) = *(const float4*)(g_wpack + PK_W11T + ch*8192 + fidx);
        }
        __syncthreads();
        gemm1x1_chunk(xs, wsm, acc, ch*64, lane, og);
        __syncthreads();
    }
    #pragma unroll
    for (int p = 0; p < 4; p++) {
        float2 v0 = unpack2(acc[p][0]), v1 = unpack2(acc[p][1]);
        float2 v2 = unpack2(acc[p][2]), v3 = unpack2(acc[p][3]);
        *(float4*)(ys + (og*8+2*p)*TT + lane*4) =
            make_float4(fmaxf(v0.x,0.f), fmaxf(v1.x,0.f), fmaxf(v2.x,0.f), fmaxf(v3.x,0.f));
        *(float4*)(ys + (og*8+2*p+1)*TT + lane*4) =
            make_float4(fmaxf(v0.y,0.f), fmaxf(v1.y,0.f), fmaxf(v2.y,0.f), fmaxf(v3.y,0.f));
    }
    __syncthreads();

    /* second 1x1 + relu -> g_y2 */
    #pragma unroll
    for (int p = 0; p < 4; p++) {
        unsigned long long v = pack2(b12[og*8+2*p], b12[og*8+2*p+1]);
        #pragma unroll
        for (int u = 0; u < 4; u++) acc[p][u] = v;
    }
    for (int ch = 0; ch < 2; ch++) {
        #pragma unroll
        for (int r = 0; r < 4; r++) {
            int fidx = (r*512 + tid) * 4;
            *(float4*)(wsm + fidx) = *(const float4*)(g_wpack + PK_W12T + ch*8192 + fidx);
        }
        __syncthreads();
        gemm1x1_chunk(ys, wsm, acc, ch*64, lane, og);
        __syncthreads();
    }
    float* y2 = g_y2 + (size_t)b * H * OW;
    #pragma unroll
    for (int p = 0; p < 4; p++) {
        float2 v0 = unpack2(acc[p][0]), v1 = unpack2(acc[p][1]);
        float2 v2 = unpack2(acc[p][2]), v3 = unpack2(acc[p][3]);
        float a0[4] = {v0.x, v1.x, v2.x, v3.x};
        float a1[4] = {v0.y, v1.y, v2.y, v3.y};
        #pragma unroll
        for (int u = 0; u < 4; u++) {
            int t = t0 + lane*4 + u;
            if (t < OW) {
                y2[(size_t)(og*8+2*p)*OW + t]   = fmaxf(a0[u], 0.f);
                y2[(size_t)(og*8+2*p+1)*OW + t] = fmaxf(a1[u], 0.f);
            }
        }
    }
}

/* ------------------------------------------------------------------ */
/* Head part 2: final conv1d (K=2, no pad) -> out [4,256,16385]       */
/* ------------------------------------------------------------------ */
__global__ void __launch_bounds__(512,1) head2_kernel(
    const float* __restrict__ bhc, float* __restrict__ out)
{
    extern __shared__ float sm[];
    float* tileA = sm;            /* y2(t)   */
    float* tileB = sm + 16384;    /* y2(t+1) */
    float* wsm   = sm + 32768;

    int b  = blockIdx.y;
    int t0 = blockIdx.x * TT;
    int tid = threadIdx.x, lane = tid & 31, og = tid >> 5;

    const float* y2 = g_y2 + (size_t)b * H * OW;
    #pragma unroll
    for (int r = 0; r < 32; r++) {
        int id = r*512 + tid;
        int c = id >> 7, tt = id & 127;
        int t  = t0 + tt;
        int t2 = t0 + tt + 1;
        tileA[c*TT + tt] = (t  < OW) ? y2[(size_t)c*OW + t]  : 0.f;
        tileB[c*TT + tt] = (t2 < OW) ? y2[(size_t)c*OW + t2] : 0.f;
    }
    __syncthreads();

    unsigned long long acca[4][4], accb[4][4];
    #pragma unroll
    for (int p = 0; p < 4; p++) {
        unsigned long long va = pack2(bhc[og*8+2*p],       bhc[og*8+2*p+1]);
        unsigned long long vb = pack2(bhc[128+og*8+2*p],   bhc[128+og*8+2*p+1]);
        #pragma unroll
        for (int u = 0; u < 4; u++) { acca[p][u] = va; accb[p][u] = vb; }
    }
    for (int ch = 0; ch < 8; ch++) {
        #pragma unroll
        for (int r = 0; r < 4; r++) {
            int fidx = (r*512 + tid) * 4;
            *(float4*)(wsm + fidx) = *(const float4*)(g_wpack + PK_WHCT + ch*(KC*256) + fidx);
        }
        __syncthreads();
        const float* xsrc = ((ch < 4) ? tileA : tileB) + ((ch & 3) * KC) * TT;
        #pragma unroll
        for (int kk = 0; kk < KC; kk++) {
            float4 xv = *(const float4*)(xsrc + kk*TT + lane*4);
            unsigned long long xp0 = pack2(xv.x, xv.x);
            unsigned long long xp1 = pack2(xv.y, xv.y);
            unsigned long long xp2 = pack2(xv.z, xv.z);
            unsigned long long xp3 = pack2(xv.w, xv.w);
            const ulonglong2* wa2 = (const ulonglong2*)(wsm + kk*256 + og*8);
            const ulonglong2* wb2 = (const ulonglong2*)(wsm + kk*256 + 128 + og*8);
            ulonglong2 waA = wa2[0], waB = wa2[1];
            ulonglong2 wbA = wb2[0], wbB = wb2[1];
            ffma2(acca[0][0], xp0, waA.x); ffma2(acca[0][1], xp1, waA.x);
            ffma2(acca[0][2], xp2, waA.x); ffma2(acca[0][3], xp3, waA.x);
            ffma2(acca[1][0], xp0, waA.y); ffma2(acca[1][1], xp1, waA.y);
            ffma2(acca[1][2], xp2, waA.y); ffma2(acca[1][3], xp3, waA.y);
            ffma2(acca[2][0], xp0, waB.x); ffma2(acca[2][1], xp1, waB.x);
            ffma2(acca[2][2], xp2, waB.x); ffma2(acca[2][3], xp3, waB.x);
            ffma2(acca[3][0], xp0, waB.y); ffma2(acca[3][1], xp1, waB.y);
            ffma2(acca[3][2], xp2, waB.y); ffma2(acca[3][3], xp3, waB.y);
            ffma2(accb[0][0], xp0, wbA.x); ffma2(accb[0][1], xp1, wbA.x);
            ffma2(accb[0][2], xp2, wbA.x); ffma2(accb[0][3], xp3, wbA.x);
            ffma2(accb[1][0], xp0, wbA.y); ffma2(accb[1][1], xp1, wbA.y);
            ffma2(accb[1][2], xp2, wbA.y); ffma2(accb[1][3], xp3, wbA.y);
            ffma2(accb[2][0], xp0, wbB.x); ffma2(accb[2][1], xp1, wbB.x);
            ffma2(accb[2][2], xp2, wbB.x); ffma2(accb[2][3], xp3, wbB.x);
            ffma2(accb[3][0], xp0, wbB.y); ffma2(accb[3][1], xp1, wbB.y);
            ffma2(accb[3][2], xp2, wbB.y); ffma2(accb[3][3], xp3, wbB.y);
        }
        __syncthreads();
    }

    const int NOUT = OW - 1;   /* 16385 */
    float* ob = out + (size_t)b * NCLS * NOUT;
    #pragma unroll
    for (int p = 0; p < 4; p++) {
        float2 a0 = unpack2(acca[p][0]), a1 = unpack2(acca[p][1]);
        float2 a2 = unpack2(acca[p][2]), a3 = unpack2(acca[p][3]);
        float2 b0 = unpack2(accb[p][0]), b1 = unpack2(accb[p][1]);
        float2 b2 = unpack2(accb[p][2]), b3 = unpack2(accb[p][3]);
        float va0[4] = {a0.x, a1.x, a2.x, a3.x};
        float va1[4] = {a0.y, a1.y, a2.y, a3.y};
        float vb0[4] = {b0.x, b1.x, b2.x, b3.x};
        float vb1[4] = {b0.y, b1.y, b2.y, b3.y};
        #pragma unroll
        for (int u = 0; u < 4; u++) {
            int t = t0 + lane*4 + u;
            if (t < NOUT) {
                ob[(size_t)(og*8+2*p)*NOUT + t]       = va0[u];
                ob[(size_t)(og*8+2*p+1)*NOUT + t]     = va1[u];
                ob[(size_t)(128+og*8+2*p)*NOUT + t]   = vb0[u];
                ob[(size_t)(128+og*8+2*p+1)*NOUT + t] = vb1[u];
            }
        }
    }
}

/* ------------------------------------------------------------------ */
extern "C" void kernel_launch(void* const* d_in, const int* in_sizes, int n_in,
                              void* d_out, int out_size)
{
    const float* x    = (const float*)d_in[0];
    const float* Wf0  = (const float*)d_in[1];
    const float* bf0  = (const float*)d_in[2];
    const float* Wg0  = (const float*)d_in[3];
    const float* bg0  = (const float*)d_in[4];
    const float* W10  = (const float*)d_in[5];
    const float* b10  = (const float*)d_in[6];
    const float* Wf   = (const float*)d_in[7];
    const float* bfA  = (const float*)d_in[8];
    const float* Wg   = (const float*)d_in[9];
    const float* bgA  = (const float*)d_in[10];
    const float* W1   = (const float*)d_in[11];
    const float* b1A  = (const float*)d_in[12];
    const float* gamma= (const float*)d_in[13];
    const float* beta = (const float*)d_in[14];
    const float* W11  = (const float*)d_in[15];
    const float* b11  = (const float*)d_in[16];
    const float* W12  = (const float*)d_in[17];
    const float* b12  = (const float*)d_in[18];
    const float* Whc  = (const float*)d_in[19];
    const float* bhc  = (const float*)d_in[20];
    float* out = (float*)d_out;

    const int SMEM_L0    = (16384 + 8192 + 132) * 4;   /*  98,832 B */
    const int SMEM_LAYER = (2*16384 + 8192) * 4;       /* 163,840 B */
    const int SMEM_HEAD  = (16384 + 16384 + 8192) * 4; /* 163,840 B */

    cudaFuncSetAttribute(layer0_kernel, cudaFuncAttributeMaxDynamicSharedMemorySize, SMEM_L0);
    cudaFuncSetAttribute(layer_kernel,  cudaFuncAttributeMaxDynamicSharedMemorySize, SMEM_LAYER);
    cudaFuncSetAttribute(head1_kernel,  cudaFuncAttributeMaxDynamicSharedMemorySize, SMEM_HEAD);
    cudaFuncSetAttribute(head2_kernel,  cudaFuncAttributeMaxDynamicSharedMemorySize, SMEM_HEAD);

    pack_kernel<<<(PK_TOTAL + 511)/512, 512>>>(Wf, Wg, W1, W10, W11, W12, Whc);
    zero_stats_kernel<<<(NLAYERS*256 + 511)/512, 512>>>();

    dim3 grid(T_LEN / TT, 4);           /* (384, 4) */
    layer0_kernel<<<grid, 512, SMEM_L0>>>(x, Wf0, bf0, Wg0, bg0, b10);
    bn_finalize_kernel<<<1, 128>>>(gamma, beta, 0);

    for (int i = 1; i < NLAYERS; i++) {
        int d = 1 << (i % 14);
        layer_kernel<<<grid, 512, SMEM_LAYER>>>(bfA, bgA, b1A, i, d);
        bn_finalize_kernel<<<1, 128>>>(gamma, beta, i);
    }

    dim3 hgrid((OW + TT - 1) / TT, 4);  /* (129, 4) */
    head1_kernel<<<hgrid, 512, SMEM_HEAD>>>(b11, b12);
    head2_kernel<<<hgrid, 512, SMEM_HEAD>>>(bhc, out);
}

// round 11
// speedup vs baseline: 1.0162x; 1.0162x over previous
#include <cuda_runtime.h>
#include <math.h>
#include <stdint.h>

#define T_LEN   49152
#define H       128
#define NCLS    256
#define OW      16386
#define SKIP_OFF 32766      /* T_LEN - OW */
#define TT      128
#define KC      32
#define NLAYERS 28

#define RES_SZ  (4*H*T_LEN)     /* 25,165,824 */
#define SKIP_SZ (4*H*OW)        /* 8,389,632  */

#define PK_LAYER  81920
#define PK_LAYERS (27*PK_LAYER)         /* 2,211,840 */
#define PK_W10T   (PK_LAYERS)
#define PK_W11T   (PK_W10T + 16384)
#define PK_W12T   (PK_W11T + 16384)
#define PK_WHCT   (PK_W12T + 16384)
#define PK_TOTAL  (PK_WHCT + 65536)     /* 2,326,528 */

__device__ __align__(16) float  g_resbuf[2][RES_SZ];
__device__ __align__(16) float  g_skip[SKIP_SZ];
__device__ __align__(16) float  g_y2[SKIP_SZ];
__device__ __align__(16) float  g_wpack[PK_TOTAL];
__device__ double g_stats[NLAYERS*256];

/* ---------------- f32x2 packed-FMA helpers (Blackwell) ------------- */
__device__ __forceinline__ void ffma2(unsigned long long &acc,
                                      unsigned long long x,
                                      unsigned long long w) {
    asm("fma.rn.f32x2 %0, %1, %2, %0;" : "+l"(acc) : "l"(x), "l"(w));
}
__device__ __forceinline__ unsigned long long pack2(float lo, float hi) {
    unsigned long long r;
    asm("mov.b64 %0, {%1, %2};" : "=l"(r) : "f"(lo), "f"(hi));
    return r;
}
__device__ __forceinline__ float2 unpack2(unsigned long long v) {
    float lo, hi;
    asm("mov.b64 {%0, %1}, %2;" : "=f"(lo), "=f"(hi) : "l"(v));
    return make_float2(lo, hi);
}
__device__ __forceinline__ float sigm(float z) { return 1.f / (1.f + expf(-z)); }

/* ------------------------------------------------------------------ */
/* Weight repack + stats zero (fused; both rerun per graph replay)    */
/* ------------------------------------------------------------------ */
__global__ void pack_kernel(const float* __restrict__ Wf, const float* __restrict__ Wg,
                            const float* __restrict__ W1, const float* __restrict__ W10,
                            const float* __restrict__ W11, const float* __restrict__ W12,
                            const float* __restrict__ Whc)
{
    int idx = blockIdx.x * blockDim.x + threadIdx.x;
    if (idx < NLAYERS*256) g_stats[idx] = 0.0;
    if (idx >= PK_TOTAL) return;
    float v;
    if (idx < PK_LAYERS) {
        int j = idx / PK_LAYER;
        int r = idx - j * PK_LAYER;
        if (r < 65536) {
            int k = r >> 8, m = r & 255;
            int tap = k >> 7, c = k & 127;
            if (m < 128) v = Wf[((j*128 + m)*128 + c)*2 + tap];
            else         v = Wg[((j*128 + (m-128))*128 + c)*2 + tap];
        } else {
            int rr = r - 65536;
            int c = rr >> 7, o = rr & 127;
            v = W1[(j*128 + o)*128 + c];
        }
    } else if (idx < PK_W11T) {
        int rr = idx - PK_W10T; int c = rr >> 7, o = rr & 127; v = W10[o*128 + c];
    } else if (idx < PK_W12T) {
        int rr = idx - PK_W11T; int c = rr >> 7, o = rr & 127; v = W11[o*128 + c];
    } else if (idx < PK_WHCT) {
        int rr = idx - PK_W12T; int c = rr >> 7, o = rr & 127; v = W12[o*128 + c];
    } else {
        int rr = idx - PK_WHCT;
        int k = rr >> 8, o = rr & 255;
        int tap = k >> 7, c = k & 127;
        v = Whc[(o*128 + c)*2 + tap];
    }
    g_wpack[idx] = v;
}

/* ------------------------------------------------------------------ */
/* stats helper: warp-reduce two (sum, sumsq) pairs, lane0 atomics    */
/* ------------------------------------------------------------------ */
__device__ __forceinline__ void stats_commit(int layer, int o0, int o1,
                                             float ls0, float lq0,
                                             float ls1, float lq1, int lane)
{
    #pragma unroll
    for (int off = 16; off; off >>= 1) {
        ls0 += __shfl_xor_sync(0xffffffffu, ls0, off);
        lq0 += __shfl_xor_sync(0xffffffffu, lq0, off);
        ls1 += __shfl_xor_sync(0xffffffffu, ls1, off);
        lq1 += __shfl_xor_sync(0xffffffffu, lq1, off);
    }
    if (lane == 0) {
        atomicAdd(&g_stats[layer*256 + o0],       (double)ls0);
        atomicAdd(&g_stats[layer*256 + 128 + o0], (double)lq0);
        atomicAdd(&g_stats[layer*256 + o1],       (double)ls1);
        atomicAdd(&g_stats[layer*256 + 128 + o1], (double)lq1);
    }
}

/* 1x1 GEMM inner chunk: 64 k-values from xs, pairs over out-channel   */
__device__ __forceinline__ void gemm1x1_chunk(const float* __restrict__ xsm,
                                              const float* __restrict__ wsm,
                                              unsigned long long acc[4][4],
                                              int cb, int lane, int og)
{
    #pragma unroll
    for (int cc = 0; cc < 64; cc++) {
        float4 xv = *(const float4*)(xsm + (cb+cc)*TT + lane*4);
        unsigned long long xp0 = pack2(xv.x, xv.x);
        unsigned long long xp1 = pack2(xv.y, xv.y);
        unsigned long long xp2 = pack2(xv.z, xv.z);
        unsigned long long xp3 = pack2(xv.w, xv.w);
        const ulonglong2* w2 = (const ulonglong2*)(wsm + cc*128 + og*8);
        ulonglong2 wA = w2[0], wB = w2[1];
        ffma2(acc[0][0], xp0, wA.x); ffma2(acc[0][1], xp1, wA.x);
        ffma2(acc[0][2], xp2, wA.x); ffma2(acc[0][3], xp3, wA.x);
        ffma2(acc[1][0], xp0, wA.y); ffma2(acc[1][1], xp1, wA.y);
        ffma2(acc[1][2], xp2, wA.y); ffma2(acc[1][3], xp3, wA.y);
        ffma2(acc[2][0], xp0, wB.x); ffma2(acc[2][1], xp1, wB.x);
        ffma2(acc[2][2], xp2, wB.x); ffma2(acc[2][3], xp3, wB.x);
        ffma2(acc[3][0], xp0, wB.y); ffma2(acc[3][1], xp1, wB.y);
        ffma2(acc[3][2], xp2, wB.y); ffma2(acc[3][3], xp3, wB.y);
    }
}

/* ------------------------------------------------------------------ */
/* Layer 0: in_channels = 1                                            */
/* ------------------------------------------------------------------ */
__global__ void __launch_bounds__(512,1) layer0_kernel(
    const float* __restrict__ x,  const float* __restrict__ Wf0,
    const float* __restrict__ bf0, const float* __restrict__ Wg0,
    const float* __restrict__ bg0, const float* __restrict__ b10)
{
    extern __shared__ float sm[];
    float* hs   = sm;                 /* 16384 */
    float* wsm  = sm + 16384;         /* 8192  */
    float* xs   = sm + 24576;         /* 132   */

    int b  = blockIdx.y;
    int t0 = blockIdx.x * TT;
    int tid = threadIdx.x, lane = tid & 31, og = tid >> 5;

    const float* xb = x + (size_t)b * T_LEN;
    if (tid < 129) {
        int t = t0 - 1 + tid;
        xs[tid] = (t >= 0) ? xb[t] : 0.f;
    }
    __syncthreads();

    /* gated conv, in_ch = 1, dilation 1 */
    #pragma unroll
    for (int i = 0; i < 8; i++) {
        int c = og*8 + i;
        float wfa = Wf0[c*2], wfb = Wf0[c*2+1];
        float wga = Wg0[c*2], wgb = Wg0[c*2+1];
        float bfv = bf0[c],   bgv = bg0[c];
        #pragma unroll
        for (int u = 0; u < 4; u++) {
            int tt = lane*4 + u;
            float xm = xs[tt], x0 = xs[tt+1];
            float zf = fmaf(wfa, xm, fmaf(wfb, x0, bfv));
            float zg = fmaf(wga, xm, fmaf(wgb, x0, bgv));
            hs[c*TT + tt] = tanhf(zf) * sigm(zg);
        }
    }
    __syncthreads();

    /* 1x1 conv */
    unsigned long long acc2[4][4];
    #pragma unroll
    for (int p = 0; p < 4; p++) {
        unsigned long long v = pack2(b10[og*8 + 2*p], b10[og*8 + 2*p + 1]);
        #pragma unroll
        for (int u = 0; u < 4; u++) acc2[p][u] = v;
    }
    const float* w1g = g_wpack + PK_W10T;
    for (int ch = 0; ch < 2; ch++) {
        #pragma unroll
        for (int r = 0; r < 4; r++) {
            int fidx = (r*512 + tid) * 4;
            *(float4*)(wsm + fidx) = *(const float4*)(w1g + ch*8192 + fidx);
        }
        __syncthreads();
        gemm1x1_chunk(hs, wsm, acc2, ch*64, lane, og);
        __syncthreads();
    }

    /* epilogue — NOTE: xs+1 is only 4B-aligned, scalar LDS only */
    float* rout = g_resbuf[0] + (size_t)b * H * T_LEN;
    float* ssb  = g_skip + (size_t)b * H * OW;
    float xr0 = xs[1 + lane*4];
    float xr1 = xs[2 + lane*4];
    float xr2 = xs[3 + lane*4];
    float xr3 = xs[4 + lane*4];
    #pragma unroll
    for (int p = 0; p < 4; p++) {
        int o0 = og*8 + 2*p, o1 = o0 + 1;
        float2 s0 = unpack2(acc2[p][0]), s1 = unpack2(acc2[p][1]);
        float2 s2 = unpack2(acc2[p][2]), s3 = unpack2(acc2[p][3]);
        float4 rv0 = make_float4(s0.x+xr0, s1.x+xr1, s2.x+xr2, s3.x+xr3);
        float4 rv1 = make_float4(s0.y+xr0, s1.y+xr1, s2.y+xr2, s3.y+xr3);
        *(float4*)(rout + (size_t)o0*T_LEN + t0 + lane*4) = rv0;
        *(float4*)(rout + (size_t)o1*T_LEN + t0 + lane*4) = rv1;
        float ls0 = rv0.x+rv0.y+rv0.z+rv0.w;
        float lq0 = rv0.x*rv0.x+rv0.y*rv0.y+rv0.z*rv0.z+rv0.w*rv0.w;
        float ls1 = rv1.x+rv1.y+rv1.z+rv1.w;
        float lq1 = rv1.x*rv1.x+rv1.y*rv1.y+rv1.z*rv1.z+rv1.w*rv1.w;
        float sk0[4] = {s0.x, s1.x, s2.x, s3.x};
        float sk1[4] = {s0.y, s1.y, s2.y, s3.y};
        #pragma unroll
        for (int u = 0; u < 4; u++) {
            int t = t0 + lane*4 + u;
            if (t >= SKIP_OFF) {
                ssb[(size_t)o0*OW + (t - SKIP_OFF)] = sk0[u];
                ssb[(size_t)o1*OW + (t - SKIP_OFF)] = sk1[u];
            }
        }
        stats_commit(0, o0, o1, ls0, lq0, ls1, lq1, lane);
    }
}

/* ------------------------------------------------------------------ */
/* Fused layer kernel (layers 1..27): per-block BN finalize, BN-folded */
/* load, gated conv (double-buffered weights), 1x1, residual, stats   */
/* ------------------------------------------------------------------ */
__global__ void __launch_bounds__(512,1) layer_kernel(
    const float* __restrict__ bfA, const float* __restrict__ bgA,
    const float* __restrict__ b1A, const float* __restrict__ gamma,
    const float* __restrict__ beta, int layer, int d)
{
    extern __shared__ float sm[];
    float* tileA = sm;
    float* tileB = sm + H*TT;
    float* wsm0  = sm + 2*H*TT;
    float* wsm1  = wsm0 + 8192;
    float* bnsc  = wsm1 + 8192;
    float* bnsh  = bnsc + 128;

    const float* resin  = g_resbuf[(layer-1) & 1];
    float*       resout = g_resbuf[layer & 1];

    int b  = blockIdx.y;
    int t0 = blockIdx.x * TT;
    int tid = threadIdx.x, lane = tid & 31, og = tid >> 5;

    /* per-block BN finalize from fp64 stats of previous layer */
    if (tid < H) {
        const double N = 4.0 * (double)T_LEN;
        double s = g_stats[(layer-1)*256 + tid];
        double q = g_stats[(layer-1)*256 + 128 + tid];
        double mean = s / N;
        double var  = q / N - mean*mean;
        float sc = gamma[(layer-1)*H + tid] * rsqrtf((float)var + 1e-5f);
        bnsc[tid] = sc;
        bnsh[tid] = fmaf(-(float)mean, sc, beta[(layer-1)*H + tid]);
    }
    __syncthreads();

    const float* src = resin + (size_t)b * H * T_LEN;

    /* load normalized input tiles: tileB = x_norm(t), tileA = x_norm(t-d) */
    if ((d & 3) == 0) {
        #pragma unroll
        for (int r = 0; r < 8; r++) {
            int c = og + 16*r;
            float s = bnsc[c], tsh = bnsh[c];
            const float* row = src + (size_t)c * T_LEN;
            float4 vB = *(const float4*)(row + t0 + lane*4);
            *(float4*)(tileB + c*TT + lane*4) =
                make_float4(fmaf(s,vB.x,tsh), fmaf(s,vB.y,tsh), fmaf(s,vB.z,tsh), fmaf(s,vB.w,tsh));
            int ta = t0 - d + lane*4;
            float4 oA = make_float4(0.f,0.f,0.f,0.f);
            if (ta >= 0) {
                float4 vA = *(const float4*)(row + ta);
                oA = make_float4(fmaf(s,vA.x,tsh), fmaf(s,vA.y,tsh), fmaf(s,vA.z,tsh), fmaf(s,vA.w,tsh));
            }
            *(float4*)(tileA + c*TT + lane*4) = oA;
        }
    } else {
        #pragma unroll
        for (int r = 0; r < 8; r++) {
            int c = og + 16*r;
            float s = bnsc[c], tsh = bnsh[c];
            const float* row = src + (size_t)c * T_LEN;
            float4 vB = *(const float4*)(row + t0 + lane*4);
            *(float4*)(tileB + c*TT + lane*4) =
                make_float4(fmaf(s,vB.x,tsh), fmaf(s,vB.y,tsh), fmaf(s,vB.z,tsh), fmaf(s,vB.w,tsh));
            #pragma unroll
            for (int u = 0; u < 4; u++) {
                int ta = t0 - d + lane*4 + u;
                tileA[c*TT + lane*4 + u] = (ta >= 0) ? fmaf(s, row[ta], tsh) : 0.f;
            }
        }
    }

    /* gated conv: M=256 (f||g), K=256 (tap0=tileA, tap1=tileB).
       Weights double-buffered: prefetch ch+1 to regs before compute(ch),
       STS after, ONE barrier per chunk. */
    unsigned long long accf[4][4], accg[4][4];
    {
        const float* bfL = bfA + (layer-1)*H;
        const float* bgL = bgA + (layer-1)*H;
        #pragma unroll
        for (int p = 0; p < 4; p++) {
            unsigned long long vf = pack2(bfL[og*8+2*p], bfL[og*8+2*p+1]);
            unsigned long long vg = pack2(bgL[og*8+2*p], bgL[og*8+2*p+1]);
            #pragma unroll
            for (int u = 0; u < 4; u++) { accf[p][u] = vf; accg[p][u] = vg; }
        }
    }
    const float* wbase = g_wpack + (size_t)(layer-1) * PK_LAYER;
    /* stage chunk 0 directly */
    #pragma unroll
    for (int r = 0; r < 4; r++) {
        int fidx = (r*512 + tid) * 4;
        *(float4*)(wsm0 + fidx) = *(const float4*)(wbase + fidx);
    }
    __syncthreads();   /* covers tiles + bn + wsm0 */

    int cur = 0;
    for (int ch = 0; ch < 8; ch++) {
        float4 pre0, pre1, pre2, pre3;
        if (ch < 7) {
            const float* wgp = wbase + (ch+1) * (KC*256);
            pre0 = *(const float4*)(wgp + (0*512 + tid)*4);
            pre1 = *(const float4*)(wgp + (1*512 + tid)*4);
            pre2 = *(const float4*)(wgp + (2*512 + tid)*4);
            pre3 = *(const float4*)(wgp + (3*512 + tid)*4);
        }
        const float* wcur = cur ? wsm1 : wsm0;
        const float* xsrc = ((ch < 4) ? tileA : tileB) + ((ch & 3) * KC) * TT;
        #pragma unroll
        for (int kk = 0; kk < KC; kk++) {
            float4 xv = *(const float4*)(xsrc + kk*TT + lane*4);
            unsigned long long xp0 = pack2(xv.x, xv.x);
            unsigned long long xp1 = pack2(xv.y, xv.y);
            unsigned long long xp2 = pack2(xv.z, xv.z);
            unsigned long long xp3 = pack2(xv.w, xv.w);
            const ulonglong2* wf2 = (const ulonglong2*)(wcur + kk*256 + og*8);
            const ulonglong2* wg2 = (const ulonglong2*)(wcur + kk*256 + 128 + og*8);
            ulonglong2 wfA = wf2[0], wfB = wf2[1];
            ulonglong2 wgA = wg2[0], wgB = wg2[1];
            ffma2(accf[0][0], xp0, wfA.x); ffma2(accf[0][1], xp1, wfA.x);
            ffma2(accf[0][2], xp2, wfA.x); ffma2(accf[0][3], xp3, wfA.x);
            ffma2(accf[1][0], xp0, wfA.y); ffma2(accf[1][1], xp1, wfA.y);
            ffma2(accf[1][2], xp2, wfA.y); ffma2(accf[1][3], xp3, wfA.y);
            ffma2(accf[2][0], xp0, wfB.x); ffma2(accf[2][1], xp1, wfB.x);
            ffma2(accf[2][2], xp2, wfB.x); ffma2(accf[2][3], xp3, wfB.x);
            ffma2(accf[3][0], xp0, wfB.y); ffma2(accf[3][1], xp1, wfB.y);
            ffma2(accf[3][2], xp2, wfB.y); ffma2(accf[3][3], xp3, wfB.y);
            ffma2(accg[0][0], xp0, wgA.x); ffma2(accg[0][1], xp1, wgA.x);
            ffma2(accg[0][2], xp2, wgA.x); ffma2(accg[0][3], xp3, wgA.x);
            ffma2(accg[1][0], xp0, wgA.y); ffma2(accg[1][1], xp1, wgA.y);
            ffma2(accg[1][2], xp2, wgA.y); ffma2(accg[1][3], xp3, wgA.y);
            ffma2(accg[2][0], xp0, wgB.x); ffma2(accg[2][1], xp1, wgB.x);
            ffma2(accg[2][2], xp2, wgB.x); ffma2(accg[2][3], xp3, wgB.x);
            ffma2(accg[3][0], xp0, wgB.y); ffma2(accg[3][1], xp1, wgB.y);
            ffma2(accg[3][2], xp2, wgB.y); ffma2(accg[3][3], xp3, wgB.y);
        }
        if (ch < 7) {
            float* wnext = cur ? wsm0 : wsm1;
            *(float4*)(wnext + (0*512 + tid)*4) = pre0;
            *(float4*)(wnext + (1*512 + tid)*4) = pre1;
            *(float4*)(wnext + (2*512 + tid)*4) = pre2;
            *(float4*)(wnext + (3*512 + tid)*4) = pre3;
            cur ^= 1;
        }
        __syncthreads();
    }

    /* gating -> hs (reuse tileA) */
    float* hs = tileA;
    #pragma unroll
    for (int p = 0; p < 4; p++) {
        float2 f0 = unpack2(accf[p][0]), f1 = unpack2(accf[p][1]);
        float2 f2 = unpack2(accf[p][2]), f3 = unpack2(accf[p][3]);
        float2 g0 = unpack2(accg[p][0]), g1 = unpack2(accg[p][1]);
        float2 g2 = unpack2(accg[p][2]), g3 = unpack2(accg[p][3]);
        float4 h0 = make_float4(tanhf(f0.x)*sigm(g0.x), tanhf(f1.x)*sigm(g1.x),
                                tanhf(f2.x)*sigm(g2.x), tanhf(f3.x)*sigm(g3.x));
        float4 h1 = make_float4(tanhf(f0.y)*sigm(g0.y), tanhf(f1.y)*sigm(g1.y),
                                tanhf(f2.y)*sigm(g2.y), tanhf(f3.y)*sigm(g3.y));
        *(float4*)(hs + (og*8+2*p)*TT + lane*4)   = h0;
        *(float4*)(hs + (og*8+2*p+1)*TT + lane*4) = h1;
    }

    /* 1x1 conv: stage chunk0, prefetch chunk1, 2 barriers total */
    unsigned long long acc2[4][4];
    {
        const float* b1L = b1A + (layer-1)*H;
        #pragma unroll
        for (int p = 0; p < 4; p++) {
            unsigned long long v = pack2(b1L[og*8+2*p], b1L[og*8+2*p+1]);
            #pragma unroll
            for (int u = 0; u < 4; u++) acc2[p][u] = v;
        }
    }
    const float* w1g = wbase + 65536;
    #pragma unroll
    for (int r = 0; r < 4; r++) {
        int fidx = (r*512 + tid) * 4;
        *(float4*)(wsm0 + fidx) = *(const float4*)(w1g + fidx);
    }
    float4 q0 = *(const float4*)(w1g + 8192 + (0*512 + tid)*4);
    float4 q1 = *(const float4*)(w1g + 8192 + (1*512 + tid)*4);
    float4 q2 = *(const float4*)(w1g + 8192 + (2*512 + tid)*4);
    float4 q3 = *(const float4*)(w1g + 8192 + (3*512 + tid)*4);
    __syncthreads();   /* hs + wsm0 ready */
    gemm1x1_chunk(hs, wsm0, acc2, 0, lane, og);
    *(float4*)(wsm1 + (0*512 + tid)*4) = q0;
    *(float4*)(wsm1 + (1*512 + tid)*4) = q1;
    *(float4*)(wsm1 + (2*512 + tid)*4) = q2;
    *(float4*)(wsm1 + (3*512 + tid)*4) = q3;
    __syncthreads();
    gemm1x1_chunk(hs, wsm1, acc2, 64, lane, og);

    /* epilogue: residual, store, BN stats, skip accumulate
       (reads only tileB, untouched since input load) */
    float* rout = resout + (size_t)b * H * T_LEN;
    float* ssb  = g_skip + (size_t)b * H * OW;
    #pragma unroll
    for (int p = 0; p < 4; p++) {
        int o0 = og*8 + 2*p, o1 = o0 + 1;
        float2 s0 = unpack2(acc2[p][0]), s1 = unpack2(acc2[p][1]);
        float2 s2 = unpack2(acc2[p][2]), s3 = unpack2(acc2[p][3]);
        float4 xB0 = *(const float4*)(tileB + o0*TT + lane*4);
        float4 xB1 = *(const float4*)(tileB + o1*TT + lane*4);
        float4 rv0 = make_float4(s0.x+xB0.x, s1.x+xB0.y, s2.x+xB0.z, s3.x+xB0.w);
        float4 rv1 = make_float4(s0.y+xB1.x, s1.y+xB1.y, s2.y+xB1.z, s3.y+xB1.w);
        *(float4*)(rout + (size_t)o0*T_LEN + t0 + lane*4) = rv0;
        *(float4*)(rout + (size_t)o1*T_LEN + t0 + lane*4) = rv1;
        float ls0 = rv0.x+rv0.y+rv0.z+rv0.w;
        float lq0 = rv0.x*rv0.x+rv0.y*rv0.y+rv0.z*rv0.z+rv0.w*rv0.w;
        float ls1 = rv1.x+rv1.y+rv1.z+rv1.w;
        float lq1 = rv1.x*rv1.x+rv1.y*rv1.y+rv1.z*rv1.z+rv1.w*rv1.w;
        float sk0[4] = {s0.x, s1.x, s2.x, s3.x};
        float sk1[4] = {s0.y, s1.y, s2.y, s3.y};
        #pragma unroll
        for (int u = 0; u < 4; u++) {
            int t = t0 + lane*4 + u;
            if (t >= SKIP_OFF) {
                ssb[(size_t)o0*OW + (t - SKIP_OFF)] += sk0[u];
                ssb[(size_t)o1*OW + (t - SKIP_OFF)] += sk1[u];
            }
        }
        stats_commit(layer, o0, o1, ls0, lq0, ls1, lq1, lane);
    }
}

/* ------------------------------------------------------------------ */
/* Head part 1: y2 = relu(W12 @ relu(W11 @ skip_sum + b11) + b12)     */
/* ------------------------------------------------------------------ */
__global__ void __launch_bounds__(512,1) head1_kernel(
    const float* __restrict__ b11, const float* __restrict__ b12)
{
    extern __shared__ float sm[];
    float* xs  = sm;
    float* ys  = sm + 16384;
    float* wsm = sm + 32768;

    int b  = blockIdx.y;
    int t0 = blockIdx.x * TT;
    int tid = threadIdx.x, lane = tid & 31, og = tid >> 5;

    const float* sk = g_skip + (size_t)b * H * OW;
    #pragma unroll
    for (int r = 0; r < 32; r++) {
        int id = r*512 + tid;
        int c = id >> 7, tt = id & 127;
        int t = t0 + tt;
        xs[c*TT + tt] = (t < OW) ? sk[(size_t)c*OW + t] : 0.f;
    }
    __syncthreads();

    unsigned long long acc[4][4];
    #pragma unroll
    for (int p = 0; p < 4; p++) {
        unsigned long long v = pack2(b11[og*8+2*p], b11[og*8+2*p+1]);
        #pragma unroll
        for (int u = 0; u < 4; u++) acc[p][u] = v;
    }
    for (int ch = 0; ch < 2; ch++) {
        #pragma unroll
        for (int r = 0; r < 4; r++) {
            int fidx = (r*512 + tid) * 4;
            *(float4*)(wsm + fidx) = *(const float4*)(g_wpack + PK_W11T + ch*8192 + fidx);
        }
        __syncthreads();
        gemm1x1_chunk(xs, wsm, acc, ch*64, lane, og);
        __syncthreads();
    }
    #pragma unroll
    for (int p = 0; p < 4; p++) {
        float2 v0 = unpack2(acc[p][0]), v1 = unpack2(acc[p][1]);
        float2 v2 = unpack2(acc[p][2]), v3 = unpack2(acc[p][3]);
        *(float4*)(ys + (og*8+2*p)*TT + lane*4) =
            make_float4(fmaxf(v0.x,0.f), fmaxf(v1.x,0.f), fmaxf(v2.x,0.f), fmaxf(v3.x,0.f));
        *(float4*)(ys + (og*8+2*p+1)*TT + lane*4) =
            make_float4(fmaxf(v0.y,0.f), fmaxf(v1.y,0.f), fmaxf(v2.y,0.f), fmaxf(v3.y,0.f));
    }
    __syncthreads();

    /* second 1x1 + relu -> g_y2 */
    #pragma unroll
    for (int p = 0; p < 4; p++) {
        unsigned long long v = pack2(b12[og*8+2*p], b12[og*8+2*p+1]);
        #pragma unroll
        for (int u = 0; u < 4; u++) acc[p][u] = v;
    }
    for (int ch = 0; ch < 2; ch++) {
        #pragma unroll
        for (int r = 0; r < 4; r++) {
            int fidx = (r*512 + tid) * 4;
            *(float4*)(wsm + fidx) = *(const float4*)(g_wpack + PK_W12T + ch*8192 + fidx);
        }
        __syncthreads();
        gemm1x1_chunk(ys, wsm, acc, ch*64, lane, og);
        __syncthreads();
    }
    float* y2 = g_y2 + (size_t)b * H * OW;
    #pragma unroll
    for (int p = 0; p < 4; p++) {
        float2 v0 = unpack2(acc[p][0]), v1 = unpack2(acc[p][1]);
        float2 v2 = unpack2(acc[p][2]), v3 = unpack2(acc[p][3]);
        float a0[4] = {v0.x, v1.x, v2.x, v3.x};
        float a1[4] = {v0.y, v1.y, v2.y, v3.y};
        #pragma unroll
        for (int u = 0; u < 4; u++) {
            int t = t0 + lane*4 + u;
            if (t < OW) {
                y2[(size_t)(og*8+2*p)*OW + t]   = fmaxf(a0[u], 0.f);
                y2[(size_t)(og*8+2*p+1)*OW + t] = fmaxf(a1[u], 0.f);
            }
        }
    }
}

/* ------------------------------------------------------------------ */
/* Head part 2: final conv1d (K=2, no pad) -> out [4,256,16385]       */
/* ------------------------------------------------------------------ */
__global__ void __launch_bounds__(512,1) head2_kernel(
    const float* __restrict__ bhc, float* __restrict__ out)
{
    extern __shared__ float sm[];
    float* tileA = sm;            /* y2(t)   */
    float* tileB = sm + 16384;    /* y2(t+1) */
    float* wsm   = sm + 32768;

    int b  = blockIdx.y;
    int t0 = blockIdx.x * TT;
    int tid = threadIdx.x, lane = tid & 31, og = tid >> 5;

    const float* y2 = g_y2 + (size_t)b * H * OW;
    #pragma unroll
    for (int r = 0; r < 32; r++) {
        int id = r*512 + tid;
        int c = id >> 7, tt = id & 127;
        int t  = t0 + tt;
        int t2 = t0 + tt + 1;
        tileA[c*TT + tt] = (t  < OW) ? y2[(size_t)c*OW + t]  : 0.f;
        tileB[c*TT + tt] = (t2 < OW) ? y2[(size_t)c*OW + t2] : 0.f;
    }
    __syncthreads();

    unsigned long long acca[4][4], accb[4][4];
    #pragma unroll
    for (int p = 0; p < 4; p++) {
        unsigned long long va = pack2(bhc[og*8+2*p],       bhc[og*8+2*p+1]);
        unsigned long long vb = pack2(bhc[128+og*8+2*p],   bhc[128+og*8+2*p+1]);
        #pragma unroll
        for (int u = 0; u < 4; u++) { acca[p][u] = va; accb[p][u] = vb; }
    }
    for (int ch = 0; ch < 8; ch++) {
        #pragma unroll
        for (int r = 0; r < 4; r++) {
            int fidx = (r*512 + tid) * 4;
            *(float4*)(wsm + fidx) = *(const float4*)(g_wpack + PK_WHCT + ch*(KC*256) + fidx);
        }
        __syncthreads();
        const float* xsrc = ((ch < 4) ? tileA : tileB) + ((ch & 3) * KC) * TT;
        #pragma unroll
        for (int kk = 0; kk < KC; kk++) {
            float4 xv = *(const float4*)(xsrc + kk*TT + lane*4);
            unsigned long long xp0 = pack2(xv.x, xv.x);
            unsigned long long xp1 = pack2(xv.y, xv.y);
            unsigned long long xp2 = pack2(xv.z, xv.z);
            unsigned long long xp3 = pack2(xv.w, xv.w);
            const ulonglong2* wa2 = (const ulonglong2*)(wsm + kk*256 + og*8);
            const ulonglong2* wb2 = (const ulonglong2*)(wsm + kk*256 + 128 + og*8);
            ulonglong2 waA = wa2[0], waB = wa2[1];
            ulonglong2 wbA = wb2[0], wbB = wb2[1];
            ffma2(acca[0][0], xp0, waA.x); ffma2(acca[0][1], xp1, waA.x);
            ffma2(acca[0][2], xp2, waA.x); ffma2(acca[0][3], xp3, waA.x);
            ffma2(acca[1][0], xp0, waA.y); ffma2(acca[1][1], xp1, waA.y);
            ffma2(acca[1][2], xp2, waA.y); ffma2(acca[1][3], xp3, waA.y);
            ffma2(acca[2][0], xp0, waB.x); ffma2(acca[2][1], xp1, waB.x);
            ffma2(acca[2][2], xp2, waB.x); ffma2(acca[2][3], xp3, waB.x);
            ffma2(acca[3][0], xp0, waB.y); ffma2(acca[3][1], xp1, waB.y);
            ffma2(acca[3][2], xp2, waB.y); ffma2(acca[3][3], xp3, waB.y);
            ffma2(accb[0][0], xp0, wbA.x); ffma2(accb[0][1], xp1, wbA.x);
            ffma2(accb[0][2], xp2, wbA.x); ffma2(accb[0][3], xp3, wbA.x);
            ffma2(accb[1][0], xp0, wbA.y); ffma2(accb[1][1], xp1, wbA.y);
            ffma2(accb[1][2], xp2, wbA.y); ffma2(accb[1][3], xp3, wbA.y);
            ffma2(accb[2][0], xp0, wbB.x); ffma2(accb[2][1], xp1, wbB.x);
            ffma2(accb[2][2], xp2, wbB.x); ffma2(accb[2][3], xp3, wbB.x);
            ffma2(accb[3][0], xp0, wbB.y); ffma2(accb[3][1], xp1, wbB.y);
            ffma2(accb[3][2], xp2, wbB.y); ffma2(accb[3][3], xp3, wbB.y);
        }
        __syncthreads();
    }

    const int NOUT = OW - 1;   /* 16385 */
    float* ob = out + (size_t)b * NCLS * NOUT;
    #pragma unroll
    for (int p = 0; p < 4; p++) {
        float2 a0 = unpack2(acca[p][0]), a1 = unpack2(acca[p][1]);
        float2 a2 = unpack2(acca[p][2]), a3 = unpack2(acca[p][3]);
        float2 b0 = unpack2(accb[p][0]), b1 = unpack2(accb[p][1]);
        float2 b2 = unpack2(accb[p][2]), b3 = unpack2(accb[p][3]);
        float va0[4] = {a0.x, a1.x, a2.x, a3.x};
        float va1[4] = {a0.y, a1.y, a2.y, a3.y};
        float vb0[4] = {b0.x, b1.x, b2.x, b3.x};
        float vb1[4] = {b0.y, b1.y, b2.y, b3.y};
        #pragma unroll
        for (int u = 0; u < 4; u++) {
            int t = t0 + lane*4 + u;
            if (t < NOUT) {
                ob[(size_t)(og*8+2*p)*NOUT + t]       = va0[u];
                ob[(size_t)(og*8+2*p+1)*NOUT + t]     = va1[u];
                ob[(size_t)(128+og*8+2*p)*NOUT + t]   = vb0[u];
                ob[(size_t)(128+og*8+2*p+1)*NOUT + t] = vb1[u];
            }
        }
    }
}

/* ------------------------------------------------------------------ */
extern "C" void kernel_launch(void* const* d_in, const int* in_sizes, int n_in,
                              void* d_out, int out_size)
{
    const float* x    = (const float*)d_in[0];
    const float* Wf0  = (const float*)d_in[1];
    const float* bf0  = (const float*)d_in[2];
    const float* Wg0  = (const float*)d_in[3];
    const float* bg0  = (const float*)d_in[4];
    const float* W10  = (const float*)d_in[5];
    const float* b10  = (const float*)d_in[6];
    const float* Wf   = (const float*)d_in[7];
    const float* bfA  = (const float*)d_in[8];
    const float* Wg   = (const float*)d_in[9];
    const float* bgA  = (const float*)d_in[10];
    const float* W1   = (const float*)d_in[11];
    const float* b1A  = (const float*)d_in[12];
    const float* gamma= (const float*)d_in[13];
    const float* beta = (const float*)d_in[14];
    const float* W11  = (const float*)d_in[15];
    const float* b11  = (const float*)d_in[16];
    const float* W12  = (const float*)d_in[17];
    const float* b12  = (const float*)d_in[18];
    const float* Whc  = (const float*)d_in[19];
    const float* bhc  = (const float*)d_in[20];
    float* out = (float*)d_out;

    const int SMEM_L0    = (16384 + 8192 + 132) * 4;            /*  98,832 B */
    const int SMEM_LAYER = (2*16384 + 2*8192 + 256) * 4;        /* 197,632 B */
    const int SMEM_HEAD  = (16384 + 16384 + 8192) * 4;          /* 163,840 B */

    cudaFuncSetAttribute(layer0_kernel, cudaFuncAttributeMaxDynamicSharedMemorySize, SMEM_L0);
    cudaFuncSetAttribute(layer_kernel,  cudaFuncAttributeMaxDynamicSharedMemorySize, SMEM_LAYER);
    cudaFuncSetAttribute(head1_kernel,  cudaFuncAttributeMaxDynamicSharedMemorySize, SMEM_HEAD);
    cudaFuncSetAttribute(head2_kernel,  cudaFuncAttributeMaxDynamicSharedMemorySize, SMEM_HEAD);

    pack_kernel<<<(PK_TOTAL + 511)/512, 512>>>(Wf, Wg, W1, W10, W11, W12, Whc);

    dim3 grid(T_LEN / TT, 4);           /* (384, 4) */
    layer0_kernel<<<grid, 512, SMEM_L0>>>(x, Wf0, bf0, Wg0, bg0, b10);

    for (int i = 1; i < NLAYERS; i++) {
        int d = 1 << (i % 14);
        layer_kernel<<<grid, 512, SMEM_LAYER>>>(bfA, bgA, b1A, gamma, beta, i, d);
    }

    dim3 hgrid((OW + TT - 1) / TT, 4);  /* (129, 4) */
    head1_kernel<<<hgrid, 512, SMEM_HEAD>>>(b11, b12);
    head2_kernel<<<hgrid, 512, SMEM_HEAD>>>(bhc, out);
}

// round 12
// speedup vs baseline: 1.0391x; 1.0226x over previous
#include <cuda_runtime.h>
#include <math.h>
#include <stdint.h>

#define T_LEN   49152
#define H       128
#define NCLS    256
#define OW      16386
#define SKIP_OFF 32766      /* T_LEN - OW */
#define TT      128
#define KC      32
#define NLAYERS 28

#define RES_SZ  (4*H*T_LEN)     /* 25,165,824 */
#define SKIP_SZ (4*H*OW)        /* 8,389,632  */

#define PK_LAYER  81920
#define PK_LAYERS (27*PK_LAYER)         /* 2,211,840 */
#define PK_W10T   (PK_LAYERS)
#define PK_W11T   (PK_W10T + 16384)
#define PK_W12T   (PK_W11T + 16384)
#define PK_WHCT   (PK_W12T + 16384)
#define PK_TOTAL  (PK_WHCT + 65536)     /* 2,326,528 */

__device__ __align__(16) float  g_resbuf[2][RES_SZ];
__device__ __align__(16) float  g_skip[SKIP_SZ];
__device__ __align__(16) float  g_y2[SKIP_SZ];
__device__ __align__(16) float  g_wpack[PK_TOTAL];
__device__ double g_stats[NLAYERS*256];

/* ---------------- f32x2 packed-FMA helpers (Blackwell) ------------- */
__device__ __forceinline__ void ffma2(unsigned long long &acc,
                                      unsigned long long x,
                                      unsigned long long w) {
    asm("fma.rn.f32x2 %0, %1, %2, %0;" : "+l"(acc) : "l"(x), "l"(w));
}
__device__ __forceinline__ unsigned long long pack2(float lo, float hi) {
    unsigned long long r;
    asm("mov.b64 %0, {%1, %2};" : "=l"(r) : "f"(lo), "f"(hi));
    return r;
}
__device__ __forceinline__ float2 unpack2(unsigned long long v) {
    float lo, hi;
    asm("mov.b64 {%0, %1}, %2;" : "=f"(lo), "=f"(hi) : "l"(v));
    return make_float2(lo, hi);
}
__device__ __forceinline__ float sigm(float z) { return 1.f / (1.f + expf(-z)); }

/* ---------------- cp.async (LDGSTS): zero-register prefetch -------- */
__device__ __forceinline__ void cp_async16(uint32_t dst_smem, const float* src) {
    asm volatile("cp.async.cg.shared.global [%0], [%1], 16;" :: "r"(dst_smem), "l"(src));
}
__device__ __forceinline__ void cp_commit() {
    asm volatile("cp.async.commit_group;");
}
__device__ __forceinline__ void cp_wait0() {
    asm volatile("cp.async.wait_group 0;");
}

/* ------------------------------------------------------------------ */
/* Weight repack + stats zero (fused; both rerun per graph replay)    */
/* ------------------------------------------------------------------ */
__global__ void pack_kernel(const float* __restrict__ Wf, const float* __restrict__ Wg,
                            const float* __restrict__ W1, const float* __restrict__ W10,
                            const float* __restrict__ W11, const float* __restrict__ W12,
                            const float* __restrict__ Whc)
{
    int idx = blockIdx.x * blockDim.x + threadIdx.x;
    if (idx < NLAYERS*256) g_stats[idx] = 0.0;
    if (idx >= PK_TOTAL) return;
    float v;
    if (idx < PK_LAYERS) {
        int j = idx / PK_LAYER;
        int r = idx - j * PK_LAYER;
        if (r < 65536) {
            int k = r >> 8, m = r & 255;
            int tap = k >> 7, c = k & 127;
            if (m < 128) v = Wf[((j*128 + m)*128 + c)*2 + tap];
            else         v = Wg[((j*128 + (m-128))*128 + c)*2 + tap];
        } else {
            int rr = r - 65536;
            int c = rr >> 7, o = rr & 127;
            v = W1[(j*128 + o)*128 + c];
        }
    } else if (idx < PK_W11T) {
        int rr = idx - PK_W10T; int c = rr >> 7, o = rr & 127; v = W10[o*128 + c];
    } else if (idx < PK_W12T) {
        int rr = idx - PK_W11T; int c = rr >> 7, o = rr & 127; v = W11[o*128 + c];
    } else if (idx < PK_WHCT) {
        int rr = idx - PK_W12T; int c = rr >> 7, o = rr & 127; v = W12[o*128 + c];
    } else {
        int rr = idx - PK_WHCT;
        int k = rr >> 8, o = rr & 255;
        int tap = k >> 7, c = k & 127;
        v = Whc[(o*128 + c)*2 + tap];
    }
    g_wpack[idx] = v;
}

/* ------------------------------------------------------------------ */
/* stats helper: warp-reduce two (sum, sumsq) pairs, lane0 atomics    */
/* ------------------------------------------------------------------ */
__device__ __forceinline__ void stats_commit(int layer, int o0, int o1,
                                             float ls0, float lq0,
                                             float ls1, float lq1, int lane)
{
    #pragma unroll
    for (int off = 16; off; off >>= 1) {
        ls0 += __shfl_xor_sync(0xffffffffu, ls0, off);
        lq0 += __shfl_xor_sync(0xffffffffu, lq0, off);
        ls1 += __shfl_xor_sync(0xffffffffu, ls1, off);
        lq1 += __shfl_xor_sync(0xffffffffu, lq1, off);
    }
    if (lane == 0) {
        atomicAdd(&g_stats[layer*256 + o0],       (double)ls0);
        atomicAdd(&g_stats[layer*256 + 128 + o0], (double)lq0);
        atomicAdd(&g_stats[layer*256 + o1],       (double)ls1);
        atomicAdd(&g_stats[layer*256 + 128 + o1], (double)lq1);
    }
}

/* 1x1 GEMM inner chunk: 64 k-values from xs, pairs over out-channel   */
__device__ __forceinline__ void gemm1x1_chunk(const float* __restrict__ xsm,
                                              const float* __restrict__ wsm,
                                              unsigned long long acc[4][4],
                                              int cb, int lane, int og)
{
    #pragma unroll
    for (int cc = 0; cc < 64; cc++) {
        float4 xv = *(const float4*)(xsm + (cb+cc)*TT + lane*4);
        unsigned long long xp0 = pack2(xv.x, xv.x);
        unsigned long long xp1 = pack2(xv.y, xv.y);
        unsigned long long xp2 = pack2(xv.z, xv.z);
        unsigned long long xp3 = pack2(xv.w, xv.w);
        const ulonglong2* w2 = (const ulonglong2*)(wsm + cc*128 + og*8);
        ulonglong2 wA = w2[0], wB = w2[1];
        ffma2(acc[0][0], xp0, wA.x); ffma2(acc[0][1], xp1, wA.x);
        ffma2(acc[0][2], xp2, wA.x); ffma2(acc[0][3], xp3, wA.x);
        ffma2(acc[1][0], xp0, wA.y); ffma2(acc[1][1], xp1, wA.y);
        ffma2(acc[1][2], xp2, wA.y); ffma2(acc[1][3], xp3, wA.y);
        ffma2(acc[2][0], xp0, wB.x); ffma2(acc[2][1], xp1, wB.x);
        ffma2(acc[2][2], xp2, wB.x); ffma2(acc[2][3], xp3, wB.x);
        ffma2(acc[3][0], xp0, wB.y); ffma2(acc[3][1], xp1, wB.y);
        ffma2(acc[3][2], xp2, wB.y); ffma2(acc[3][3], xp3, wB.y);
    }
}

/* ------------------------------------------------------------------ */
/* Layer 0: in_channels = 1                                            */
/* ------------------------------------------------------------------ */
__global__ void __launch_bounds__(512,1) layer0_kernel(
    const float* __restrict__ x,  const float* __restrict__ Wf0,
    const float* __restrict__ bf0, const float* __restrict__ Wg0,
    const float* __restrict__ bg0, const float* __restrict__ b10)
{
    extern __shared__ float sm[];
    float* hs   = sm;                 /* 16384 */
    float* wsm  = sm + 16384;         /* 8192  */
    float* xs   = sm + 24576;         /* 132   */

    int b  = blockIdx.y;
    int t0 = blockIdx.x * TT;
    int tid = threadIdx.x, lane = tid & 31, og = tid >> 5;

    const float* xb = x + (size_t)b * T_LEN;
    if (tid < 129) {
        int t = t0 - 1 + tid;
        xs[tid] = (t >= 0) ? xb[t] : 0.f;
    }
    __syncthreads();

    /* gated conv, in_ch = 1, dilation 1 */
    #pragma unroll
    for (int i = 0; i < 8; i++) {
        int c = og*8 + i;
        float wfa = Wf0[c*2], wfb = Wf0[c*2+1];
        float wga = Wg0[c*2], wgb = Wg0[c*2+1];
        float bfv = bf0[c],   bgv = bg0[c];
        #pragma unroll
        for (int u = 0; u < 4; u++) {
            int tt = lane*4 + u;
            float xm = xs[tt], x0 = xs[tt+1];
            float zf = fmaf(wfa, xm, fmaf(wfb, x0, bfv));
            float zg = fmaf(wga, xm, fmaf(wgb, x0, bgv));
            hs[c*TT + tt] = tanhf(zf) * sigm(zg);
        }
    }
    __syncthreads();

    /* 1x1 conv */
    unsigned long long acc2[4][4];
    #pragma unroll
    for (int p = 0; p < 4; p++) {
        unsigned long long v = pack2(b10[og*8 + 2*p], b10[og*8 + 2*p + 1]);
        #pragma unroll
        for (int u = 0; u < 4; u++) acc2[p][u] = v;
    }
    const float* w1g = g_wpack + PK_W10T;
    for (int ch = 0; ch < 2; ch++) {
        #pragma unroll
        for (int r = 0; r < 4; r++) {
            int fidx = (r*512 + tid) * 4;
            *(float4*)(wsm + fidx) = *(const float4*)(w1g + ch*8192 + fidx);
        }
        __syncthreads();
        gemm1x1_chunk(hs, wsm, acc2, ch*64, lane, og);
        __syncthreads();
    }

    /* epilogue — NOTE: xs+1 is only 4B-aligned, scalar LDS only */
    float* rout = g_resbuf[0] + (size_t)b * H * T_LEN;
    float* ssb  = g_skip + (size_t)b * H * OW;
    float xr0 = xs[1 + lane*4];
    float xr1 = xs[2 + lane*4];
    float xr2 = xs[3 + lane*4];
    float xr3 = xs[4 + lane*4];
    #pragma unroll
    for (int p = 0; p < 4; p++) {
        int o0 = og*8 + 2*p, o1 = o0 + 1;
        float2 s0 = unpack2(acc2[p][0]), s1 = unpack2(acc2[p][1]);
        float2 s2 = unpack2(acc2[p][2]), s3 = unpack2(acc2[p][3]);
        float4 rv0 = make_float4(s0.x+xr0, s1.x+xr1, s2.x+xr2, s3.x+xr3);
        float4 rv1 = make_float4(s0.y+xr0, s1.y+xr1, s2.y+xr2, s3.y+xr3);
        *(float4*)(rout + (size_t)o0*T_LEN + t0 + lane*4) = rv0;
        *(float4*)(rout + (size_t)o1*T_LEN + t0 + lane*4) = rv1;
        float ls0 = rv0.x+rv0.y+rv0.z+rv0.w;
        float lq0 = rv0.x*rv0.x+rv0.y*rv0.y+rv0.z*rv0.z+rv0.w*rv0.w;
        float ls1 = rv1.x+rv1.y+rv1.z+rv1.w;
        float lq1 = rv1.x*rv1.x+rv1.y*rv1.y+rv1.z*rv1.z+rv1.w*rv1.w;
        float sk0[4] = {s0.x, s1.x, s2.x, s3.x};
        float sk1[4] = {s0.y, s1.y, s2.y, s3.y};
        #pragma unroll
        for (int u = 0; u < 4; u++) {
            int t = t0 + lane*4 + u;
            if (t >= SKIP_OFF) {
                ssb[(size_t)o0*OW + (t - SKIP_OFF)] = sk0[u];
                ssb[(size_t)o1*OW + (t - SKIP_OFF)] = sk1[u];
            }
        }
        stats_commit(0, o0, o1, ls0, lq0, ls1, lq1, lane);
    }
}

/* ------------------------------------------------------------------ */
/* Fused layer kernel (layers 1..27): per-block BN finalize, BN-folded */
/* load, gated conv (cp.async double-buffered weights), 1x1, residual */
/* ------------------------------------------------------------------ */
__global__ void __launch_bounds__(512,1) layer_kernel(
    const float* __restrict__ bfA, const float* __restrict__ bgA,
    const float* __restrict__ b1A, const float* __restrict__ gamma,
    const float* __restrict__ beta, int layer, int d)
{
    extern __shared__ float sm[];
    float* tileA = sm;
    float* tileB = sm + H*TT;
    float* wsm0  = sm + 2*H*TT;
    float* wsm1  = wsm0 + 8192;
    float* bnsc  = wsm1 + 8192;
    float* bnsh  = bnsc + 128;

    const float* resin  = g_resbuf[(layer-1) & 1];
    float*       resout = g_resbuf[layer & 1];

    int b  = blockIdx.y;
    int t0 = blockIdx.x * TT;
    int tid = threadIdx.x, lane = tid & 31, og = tid >> 5;

    uint32_t wsm0_u = (uint32_t)__cvta_generic_to_shared(wsm0);
    uint32_t wsm1_u = (uint32_t)__cvta_generic_to_shared(wsm1);

    /* per-block BN finalize from fp64 stats of previous layer */
    if (tid < H) {
        const double N = 4.0 * (double)T_LEN;
        double s = g_stats[(layer-1)*256 + tid];
        double q = g_stats[(layer-1)*256 + 128 + tid];
        double mean = s / N;
        double var  = q / N - mean*mean;
        float sc = gamma[(layer-1)*H + tid] * rsqrtf((float)var + 1e-5f);
        bnsc[tid] = sc;
        bnsh[tid] = fmaf(-(float)mean, sc, beta[(layer-1)*H + tid]);
    }
    __syncthreads();

    const float* src = resin + (size_t)b * H * T_LEN;
    const float* wbase = g_wpack + (size_t)(layer-1) * PK_LAYER;

    /* kick off chunk-0 weight stage with cp.async before tile loads */
    {
        cp_async16(wsm0_u + (0*512 + tid)*16, wbase + (0*512 + tid)*4);
        cp_async16(wsm0_u + (1*512 + tid)*16, wbase + (1*512 + tid)*4);
        cp_async16(wsm0_u + (2*512 + tid)*16, wbase + (2*512 + tid)*4);
        cp_async16(wsm0_u + (3*512 + tid)*16, wbase + (3*512 + tid)*4);
        cp_commit();
    }

    /* load normalized input tiles: tileB = x_norm(t), tileA = x_norm(t-d) */
    if ((d & 3) == 0) {
        #pragma unroll
        for (int r = 0; r < 8; r++) {
            int c = og + 16*r;
            float s = bnsc[c], tsh = bnsh[c];
            const float* row = src + (size_t)c * T_LEN;
            float4 vB = *(const float4*)(row + t0 + lane*4);
            *(float4*)(tileB + c*TT + lane*4) =
                make_float4(fmaf(s,vB.x,tsh), fmaf(s,vB.y,tsh), fmaf(s,vB.z,tsh), fmaf(s,vB.w,tsh));
            int ta = t0 - d + lane*4;
            float4 oA = make_float4(0.f,0.f,0.f,0.f);
            if (ta >= 0) {
                float4 vA = *(const float4*)(row + ta);
                oA = make_float4(fmaf(s,vA.x,tsh), fmaf(s,vA.y,tsh), fmaf(s,vA.z,tsh), fmaf(s,vA.w,tsh));
            }
            *(float4*)(tileA + c*TT + lane*4) = oA;
        }
    } else {
        #pragma unroll
        for (int r = 0; r < 8; r++) {
            int c = og + 16*r;
            float s = bnsc[c], tsh = bnsh[c];
            const float* row = src + (size_t)c * T_LEN;
            float4 vB = *(const float4*)(row + t0 + lane*4);
            *(float4*)(tileB + c*TT + lane*4) =
                make_float4(fmaf(s,vB.x,tsh), fmaf(s,vB.y,tsh), fmaf(s,vB.z,tsh), fmaf(s,vB.w,tsh));
            #pragma unroll
            for (int u = 0; u < 4; u++) {
                int ta = t0 - d + lane*4 + u;
                tileA[c*TT + lane*4 + u] = (ta >= 0) ? fmaf(s, row[ta], tsh) : 0.f;
            }
        }
    }

    /* gated conv: M=256 (f||g), K=256 (tap0=tileA, tap1=tileB).
       Weights double-buffered via cp.async: issue prefetch of ch+1 into
       wnext at top of chunk (no registers held), compute ch from wcur,
       wait, ONE barrier per chunk. */
    unsigned long long accf[4][4], accg[4][4];
    {
        const float* bfL = bfA + (layer-1)*H;
        const float* bgL = bgA + (layer-1)*H;
        #pragma unroll
        for (int p = 0; p < 4; p++) {
            unsigned long long vf = pack2(bfL[og*8+2*p], bfL[og*8+2*p+1]);
            unsigned long long vg = pack2(bgL[og*8+2*p], bgL[og*8+2*p+1]);
            #pragma unroll
            for (int u = 0; u < 4; u++) { accf[p][u] = vf; accg[p][u] = vg; }
        }
    }
    cp_wait0();
    __syncthreads();   /* covers tiles + bn + wsm0 */

    int cur = 0;
    for (int ch = 0; ch < 8; ch++) {
        if (ch < 7) {
            const float* wgp = wbase + (ch+1) * (KC*256);
            uint32_t wn = cur ? wsm0_u : wsm1_u;
            cp_async16(wn + (0*512 + tid)*16, wgp + (0*512 + tid)*4);
            cp_async16(wn + (1*512 + tid)*16, wgp + (1*512 + tid)*4);
            cp_async16(wn + (2*512 + tid)*16, wgp + (2*512 + tid)*4);
            cp_async16(wn + (3*512 + tid)*16, wgp + (3*512 + tid)*4);
            cp_commit();
        }
        const float* wcur = cur ? wsm1 : wsm0;
        const float* xsrc = ((ch < 4) ? tileA : tileB) + ((ch & 3) * KC) * TT;
        #pragma unroll
        for (int kk = 0; kk < KC; kk++) {
            float4 xv = *(const float4*)(xsrc + kk*TT + lane*4);
            unsigned long long xp0 = pack2(xv.x, xv.x);
            unsigned long long xp1 = pack2(xv.y, xv.y);
            unsigned long long xp2 = pack2(xv.z, xv.z);
            unsigned long long xp3 = pack2(xv.w, xv.w);
            const ulonglong2* wf2 = (const ulonglong2*)(wcur + kk*256 + og*8);
            const ulonglong2* wg2 = (const ulonglong2*)(wcur + kk*256 + 128 + og*8);
            ulonglong2 wfA = wf2[0], wfB = wf2[1];
            ulonglong2 wgA = wg2[0], wgB = wg2[1];
            ffma2(accf[0][0], xp0, wfA.x); ffma2(accf[0][1], xp1, wfA.x);
            ffma2(accf[0][2], xp2, wfA.x); ffma2(accf[0][3], xp3, wfA.x);
            ffma2(accf[1][0], xp0, wfA.y); ffma2(accf[1][1], xp1, wfA.y);
            ffma2(accf[1][2], xp2, wfA.y); ffma2(accf[1][3], xp3, wfA.y);
            ffma2(accf[2][0], xp0, wfB.x); ffma2(accf[2][1], xp1, wfB.x);
            ffma2(accf[2][2], xp2, wfB.x); ffma2(accf[2][3], xp3, wfB.x);
            ffma2(accf[3][0], xp0, wfB.y); ffma2(accf[3][1], xp1, wfB.y);
            ffma2(accf[3][2], xp2, wfB.y); ffma2(accf[3][3], xp3, wfB.y);
            ffma2(accg[0][0], xp0, wgA.x); ffma2(accg[0][1], xp1, wgA.x);
            ffma2(accg[0][2], xp2, wgA.x); ffma2(accg[0][3], xp3, wgA.x);
            ffma2(accg[1][0], xp0, wgA.y); ffma2(accg[1][1], xp1, wgA.y);
            ffma2(accg[1][2], xp2, wgA.y); ffma2(accg[1][3], xp3, wgA.y);
            ffma2(accg[2][0], xp0, wgB.x); ffma2(accg[2][1], xp1, wgB.x);
            ffma2(accg[2][2], xp2, wgB.x); ffma2(accg[2][3], xp3, wgB.x);
            ffma2(accg[3][0], xp0, wgB.y); ffma2(accg[3][1], xp1, wgB.y);
            ffma2(accg[3][2], xp2, wgB.y); ffma2(accg[3][3], xp3, wgB.y);
        }
        if (ch < 7) { cp_wait0(); cur ^= 1; }
        __syncthreads();
    }

    /* gating -> hs (reuse tileA) */
    float* hs = tileA;
    #pragma unroll
    for (int p = 0; p < 4; p++) {
        float2 f0 = unpack2(accf[p][0]), f1 = unpack2(accf[p][1]);
        float2 f2 = unpack2(accf[p][2]), f3 = unpack2(accf[p][3]);
        float2 g0 = unpack2(accg[p][0]), g1 = unpack2(accg[p][1]);
        float2 g2 = unpack2(accg[p][2]), g3 = unpack2(accg[p][3]);
        float4 h0 = make_float4(tanhf(f0.x)*sigm(g0.x), tanhf(f1.x)*sigm(g1.x),
                                tanhf(f2.x)*sigm(g2.x), tanhf(f3.x)*sigm(g3.x));
        float4 h1 = make_float4(tanhf(f0.y)*sigm(g0.y), tanhf(f1.y)*sigm(g1.y),
                                tanhf(f2.y)*sigm(g2.y), tanhf(f3.y)*sigm(g3.y));
        *(float4*)(hs + (og*8+2*p)*TT + lane*4)   = h0;
        *(float4*)(hs + (og*8+2*p+1)*TT + lane*4) = h1;
    }

    /* 1x1 conv: chunk0 staged to wsm0 + chunk1 via cp.async to wsm1 */
    unsigned long long acc2[4][4];
    {
        const float* b1L = b1A + (layer-1)*H;
        #pragma unroll
        for (int p = 0; p < 4; p++) {
            unsigned long long v = pack2(b1L[og*8+2*p], b1L[og*8+2*p+1]);
            #pragma unroll
            for (int u = 0; u < 4; u++) acc2[p][u] = v;
        }
    }
    const float* w1g = wbase + 65536;
    cp_async16(wsm0_u + (0*512 + tid)*16, w1g + (0*512 + tid)*4);
    cp_async16(wsm0_u + (1*512 + tid)*16, w1g + (1*512 + tid)*4);
    cp_async16(wsm0_u + (2*512 + tid)*16, w1g + (2*512 + tid)*4);
    cp_async16(wsm0_u + (3*512 + tid)*16, w1g + (3*512 + tid)*4);
    cp_commit();
    cp_async16(wsm1_u + (0*512 + tid)*16, w1g + 8192 + (0*512 + tid)*4);
    cp_async16(wsm1_u + (1*512 + tid)*16, w1g + 8192 + (1*512 + tid)*4);
    cp_async16(wsm1_u + (2*512 + tid)*16, w1g + 8192 + (2*512 + tid)*4);
    cp_async16(wsm1_u + (3*512 + tid)*16, w1g + 8192 + (3*512 + tid)*4);
    cp_commit();
    asm volatile("cp.async.wait_group 1;");   /* wsm0 landed */
    __syncthreads();   /* hs + wsm0 ready */
    gemm1x1_chunk(hs, wsm0, acc2, 0, lane, og);
    cp_wait0();                               /* wsm1 landed */
    __syncthreads();
    gemm1x1_chunk(hs, wsm1, acc2, 64, lane, og);

    /* epilogue: residual, store, BN stats, skip accumulate
       (reads only tileB, untouched since input load) */
    float* rout = resout + (size_t)b * H * T_LEN;
    float* ssb  = g_skip + (size_t)b * H * OW;
    #pragma unroll
    for (int p = 0; p < 4; p++) {
        int o0 = og*8 + 2*p, o1 = o0 + 1;
        float2 s0 = unpack2(acc2[p][0]), s1 = unpack2(acc2[p][1]);
        float2 s2 = unpack2(acc2[p][2]), s3 = unpack2(acc2[p][3]);
        float4 xB0 = *(const float4*)(tileB + o0*TT + lane*4);
        float4 xB1 = *(const float4*)(tileB + o1*TT + lane*4);
        float4 rv0 = make_float4(s0.x+xB0.x, s1.x+xB0.y, s2.x+xB0.z, s3.x+xB0.w);
        float4 rv1 = make_float4(s0.y+xB1.x, s1.y+xB1.y, s2.y+xB1.z, s3.y+xB1.w);
        *(float4*)(rout + (size_t)o0*T_LEN + t0 + lane*4) = rv0;
        *(float4*)(rout + (size_t)o1*T_LEN + t0 + lane*4) = rv1;
        float ls0 = rv0.x+rv0.y+rv0.z+rv0.w;
        float lq0 = rv0.x*rv0.x+rv0.y*rv0.y+rv0.z*rv0.z+rv0.w*rv0.w;
        float ls1 = rv1.x+rv1.y+rv1.z+rv1.w;
        float lq1 = rv1.x*rv1.x+rv1.y*rv1.y+rv1.z*rv1.z+rv1.w*rv1.w;
        float sk0[4] = {s0.x, s1.x, s2.x, s3.x};
        float sk1[4] = {s0.y, s1.y, s2.y, s3.y};
        #pragma unroll
        for (int u = 0; u < 4; u++) {
            int t = t0 + lane*4 + u;
            if (t >= SKIP_OFF) {
                ssb[(size_t)o0*OW + (t - SKIP_OFF)] += sk0[u];
                ssb[(size_t)o1*OW + (t - SKIP_OFF)] += sk1[u];
            }
        }
        stats_commit(layer, o0, o1, ls0, lq0, ls1, lq1, lane);
    }
}

/* ------------------------------------------------------------------ */
/* Head part 1: y2 = relu(W12 @ relu(W11 @ skip_sum + b11) + b12)     */
/* ------------------------------------------------------------------ */
__global__ void __launch_bounds__(512,1) head1_kernel(
    const float* __restrict__ b11, const float* __restrict__ b12)
{
    extern __shared__ float sm[];
    float* xs  = sm;
    float* ys  = sm + 16384;
    float* wsm = sm + 32768;

    int b  = blockIdx.y;
    int t0 = blockIdx.x * TT;
    int tid = threadIdx.x, lane = tid & 31, og = tid >> 5;

    const float* sk = g_skip + (size_t)b * H * OW;
    #pragma unroll
    for (int r = 0; r < 32; r++) {
        int id = r*512 + tid;
        int c = id >> 7, tt = id & 127;
        int t = t0 + tt;
        xs[c*TT + tt] = (t < OW) ? sk[(size_t)c*OW + t] : 0.f;
    }
    __syncthreads();

    unsigned long long acc[4][4];
    #pragma unroll
    for (int p = 0; p < 4; p++) {
        unsigned long long v = pack2(b11[og*8+2*p], b11[og*8+2*p+1]);
        #pragma unroll
        for (int u = 0; u < 4; u++) acc[p][u] = v;
    }
    for (int ch = 0; ch < 2; ch++) {
        #pragma unroll
        for (int r = 0; r < 4; r++) {
            int fidx = (r*512 + tid) * 4;
            *(float4*)(wsm + fidx) = *(const float4*)(g_wpack + PK_W11T + ch*8192 + fidx);
        }
        __syncthreads();
        gemm1x1_chunk(xs, wsm, acc, ch*64, lane, og);
        __syncthreads();
    }
    #pragma unroll
    for (int p = 0; p < 4; p++) {
        float2 v0 = unpack2(acc[p][0]), v1 = unpack2(acc[p][1]);
        float2 v2 = unpack2(acc[p][2]), v3 = unpack2(acc[p][3]);
        *(float4*)(ys + (og*8+2*p)*TT + lane*4) =
            make_float4(fmaxf(v0.x,0.f), fmaxf(v1.x,0.f), fmaxf(v2.x,0.f), fmaxf(v3.x,0.f));
        *(float4*)(ys + (og*8+2*p+1)*TT + lane*4) =
            make_float4(fmaxf(v0.y,0.f), fmaxf(v1.y,0.f), fmaxf(v2.y,0.f), fmaxf(v3.y,0.f));
    }
    __syncthreads();

    /* second 1x1 + relu -> g_y2 */
    #pragma unroll
    for (int p = 0; p < 4; p++) {
        unsigned long long v = pack2(b12[og*8+2*p], b12[og*8+2*p+1]);
        #pragma unroll
        for (int u = 0; u < 4; u++) acc[p][u] = v;
    }
    for (int ch = 0; ch < 2; ch++) {
        #pragma unroll
        for (int r = 0; r < 4; r++) {
            int fidx = (r*512 + tid) * 4;
            *(float4*)(wsm + fidx) = *(const float4*)(g_wpack + PK_W12T + ch*8192 + fidx);
        }
        __syncthreads();
        gemm1x1_chunk(ys, wsm, acc, ch*64, lane, og);
        __syncthreads();
    }
    float* y2 = g_y2 + (size_t)b * H * OW;
    #pragma unroll
    for (int p = 0; p < 4; p++) {
        float2 v0 = unpack2(acc[p][0]), v1 = unpack2(acc[p][1]);
        float2 v2 = unpack2(acc[p][2]), v3 = unpack2(acc[p][3]);
        float a0[4] = {v0.x, v1.x, v2.x, v3.x};
        float a1[4] = {v0.y, v1.y, v2.y, v3.y};
        #pragma unroll
        for (int u = 0; u < 4; u++) {
            int t = t0 + lane*4 + u;
            if (t < OW) {
                y2[(size_t)(og*8+2*p)*OW + t]   = fmaxf(a0[u], 0.f);
                y2[(size_t)(og*8+2*p+1)*OW + t] = fmaxf(a1[u], 0.f);
            }
        }
    }
}

/* ------------------------------------------------------------------ */
/* Head part 2: final conv1d (K=2, no pad) -> out [4,256,16385]       */
/* ------------------------------------------------------------------ */
__global__ void __launch_bounds__(512,1) head2_kernel(
    const float* __restrict__ bhc, float* __restrict__ out)
{
    extern __shared__ float sm[];
    float* tileA = sm;            /* y2(t)   */
    float* tileB = sm + 16384;    /* y2(t+1) */
    float* wsm   = sm + 32768;

    int b  = blockIdx.y;
    int t0 = blockIdx.x * TT;
    int tid = threadIdx.x, lane = tid & 31, og = tid >> 5;

    const float* y2 = g_y2 + (size_t)b * H * OW;
    #pragma unroll
    for (int r = 0; r < 32; r++) {
        int id = r*512 + tid;
        int c = id >> 7, tt = id & 127;
        int t  = t0 + tt;
        int t2 = t0 + tt + 1;
        tileA[c*TT + tt] = (t  < OW) ? y2[(size_t)c*OW + t]  : 0.f;
        tileB[c*TT + tt] = (t2 < OW) ? y2[(size_t)c*OW + t2] : 0.f;
    }
    __syncthreads();

    unsigned long long acca[4][4], accb[4][4];
    #pragma unroll
    for (int p = 0; p < 4; p++) {
        unsigned long long va = pack2(bhc[og*8+2*p],       bhc[og*8+2*p+1]);
        unsigned long long vb = pack2(bhc[128+og*8+2*p],   bhc[128+og*8+2*p+1]);
        #pragma unroll
        for (int u = 0; u < 4; u++) { acca[p][u] = va; accb[p][u] = vb; }
    }
    for (int ch = 0; ch < 8; ch++) {
        #pragma unroll
        for (int r = 0; r < 4; r++) {
            int fidx = (r*512 + tid) * 4;
            *(float4*)(wsm + fidx) = *(const float4*)(g_wpack + PK_WHCT + ch*(KC*256) + fidx);
        }
        __syncthreads();
        const float* xsrc = ((ch < 4) ? tileA : tileB) + ((ch & 3) * KC) * TT;
        #pragma unroll
        for (int kk = 0; kk < KC; kk++) {
            float4 xv = *(const float4*)(xsrc + kk*TT + lane*4);
            unsigned long long xp0 = pack2(xv.x, xv.x);
            unsigned long long xp1 = pack2(xv.y, xv.y);
            unsigned long long xp2 = pack2(xv.z, xv.z);
            unsigned long long xp3 = pack2(xv.w, xv.w);
            const ulonglong2* wa2 = (const ulonglong2*)(wsm + kk*256 + og*8);
            const ulonglong2* wb2 = (const ulonglong2*)(wsm + kk*256 + 128 + og*8);
            ulonglong2 waA = wa2[0], waB = wa2[1];
            ulonglong2 wbA = wb2[0], wbB = wb2[1];
            ffma2(acca[0][0], xp0, waA.x); ffma2(acca[0][1], xp1, waA.x);
            ffma2(acca[0][2], xp2, waA.x); ffma2(acca[0][3], xp3, waA.x);
            ffma2(acca[1][0], xp0, waA.y); ffma2(acca[1][1], xp1, waA.y);
            ffma2(acca[1][2], xp2, waA.y); ffma2(acca[1][3], xp3, waA.y);
            ffma2(acca[2][0], xp0, waB.x); ffma2(acca[2][1], xp1, waB.x);
            ffma2(acca[2][2], xp2, waB.x); ffma2(acca[2][3], xp3, waB.x);
            ffma2(acca[3][0], xp0, waB.y); ffma2(acca[3][1], xp1, waB.y);
            ffma2(acca[3][2], xp2, waB.y); ffma2(acca[3][3], xp3, waB.y);
            ffma2(accb[0][0], xp0, wbA.x); ffma2(accb[0][1], xp1, wbA.x);
            ffma2(accb[0][2], xp2, wbA.x); ffma2(accb[0][3], xp3, wbA.x);
            ffma2(accb[1][0], xp0, wbA.y); ffma2(accb[1][1], xp1, wbA.y);
            ffma2(accb[1][2], xp2, wbA.y); ffma2(accb[1][3], xp3, wbA.y);
            ffma2(accb[2][0], xp0, wbB.x); ffma2(accb[2][1], xp1, wbB.x);
            ffma2(accb[2][2], xp2, wbB.x); ffma2(accb[2][3], xp3, wbB.x);
            ffma2(accb[3][0], xp0, wbB.y); ffma2(accb[3][1], xp1, wbB.y);
            ffma2(accb[3][2], xp2, wbB.y); ffma2(accb[3][3], xp3, wbB.y);
        }
        __syncthreads();
    }

    const int NOUT = OW - 1;   /* 16385 */
    float* ob = out + (size_t)b * NCLS * NOUT;
    #pragma unroll
    for (int p = 0; p < 4; p++) {
        float2 a0 = unpack2(acca[p][0]), a1 = unpack2(acca[p][1]);
        float2 a2 = unpack2(acca[p][2]), a3 = unpack2(acca[p][3]);
        float2 b0 = unpack2(accb[p][0]), b1 = unpack2(accb[p][1]);
        float2 b2 = unpack2(accb[p][2]), b3 = unpack2(accb[p][3]);
        float va0[4] = {a0.x, a1.x, a2.x, a3.x};
        float va1[4] = {a0.y, a1.y, a2.y, a3.y};
        float vb0[4] = {b0.x, b1.x, b2.x, b3.x};
        float vb1[4] = {b0.y, b1.y, b2.y, b3.y};
        #pragma unroll
        for (int u = 0; u < 4; u++) {
            int t = t0 + lane*4 + u;
            if (t < NOUT) {
                ob[(size_t)(og*8+2*p)*NOUT + t]       = va0[u];
                ob[(size_t)(og*8+2*p+1)*NOUT + t]     = va1[u];
                ob[(size_t)(128+og*8+2*p)*NOUT + t]   = vb0[u];
                ob[(size_t)(128+og*8+2*p+1)*NOUT + t] = vb1[u];
            }
        }
    }
}

/* ------------------------------------------------------------------ */
extern "C" void kernel_launch(void* const* d_in, const int* in_sizes, int n_in,
                              void* d_out, int out_size)
{
    const float* x    = (const float*)d_in[0];
    const float* Wf0  = (const float*)d_in[1];
    const float* bf0  = (const float*)d_in[2];
    const float* Wg0  = (const float*)d_in[3];
    const float* bg0  = (const float*)d_in[4];
    const float* W10  = (const float*)d_in[5];
    const float* b10  = (const float*)d_in[6];
    const float* Wf   = (const float*)d_in[7];
    const float* bfA  = (const float*)d_in[8];
    const float* Wg   = (const float*)d_in[9];
    const float* bgA  = (const float*)d_in[10];
    const float* W1   = (const float*)d_in[11];
    const float* b1A  = (const float*)d_in[12];
    const float* gamma= (const float*)d_in[13];
    const float* beta = (const float*)d_in[14];
    const float* W11  = (const float*)d_in[15];
    const float* b11  = (const float*)d_in[16];
    const float* W12  = (const float*)d_in[17];
    const float* b12  = (const float*)d_in[18];
    const float* Whc  = (const float*)d_in[19];
    const float* bhc  = (const float*)d_in[20];
    float* out = (float*)d_out;

    const int SMEM_L0    = (16384 + 8192 + 132) * 4;            /*  98,832 B */
    const int SMEM_LAYER = (2*16384 + 2*8192 + 256) * 4;        /* 197,632 B */
    const int SMEM_HEAD  = (16384 + 16384 + 8192) * 4;          /* 163,840 B */

    cudaFuncSetAttribute(layer0_kernel, cudaFuncAttributeMaxDynamicSharedMemorySize, SMEM_L0);
    cudaFuncSetAttribute(layer_kernel,  cudaFuncAttributeMaxDynamicSharedMemorySize, SMEM_LAYER);
    cudaFuncSetAttribute(head1_kernel,  cudaFuncAttributeMaxDynamicSharedMemorySize, SMEM_HEAD);
    cudaFuncSetAttribute(head2_kernel,  cudaFuncAttributeMaxDynamicSharedMemorySize, SMEM_HEAD);

    pack_kernel<<<(PK_TOTAL + 511)/512, 512>>>(Wf, Wg, W1, W10, W11, W12, Whc);

    dim3 grid(T_LEN / TT, 4);           /* (384, 4) */
    layer0_kernel<<<grid, 512, SMEM_L0>>>(x, Wf0, bf0, Wg0, bg0, b10);

    for (int i = 1; i < NLAYERS; i++) {
        int d = 1 << (i % 14);
        layer_kernel<<<grid, 512, SMEM_LAYER>>>(bfA, bgA, b1A, gamma, beta, i, d);
    }

    dim3 hgrid((OW + TT - 1) / TT, 4);  /* (129, 4) */
    head1_kernel<<<hgrid, 512, SMEM_HEAD>>>(b11, b12);
    head2_kernel<<<hgrid, 512, SMEM_HEAD>>>(bhc, out);
}

// round 16
// speedup vs baseline: 1.0739x; 1.0335x over previous
#include <cuda_runtime.h>
#include <math.h>
#include <stdint.h>

#define T_LEN   49152
#define H       128
#define NCLS    256
#define OW      16386
#define SKIP_OFF 32766      /* T_LEN - OW */
#define TT      128
#define KC      32
#define NLAYERS 28

#define RES_SZ  (4*H*T_LEN)     /* 25,165,824 */
#define SKIP_SZ (4*H*OW)        /* 8,389,632  */

#define PK_LAYER  81920
#define PK_LAYERS (27*PK_LAYER)         /* 2,211,840 */
#define PK_W10T   (PK_LAYERS)
#define PK_W11T   (PK_W10T + 16384)
#define PK_W12T   (PK_W11T + 16384)
#define PK_WHCT   (PK_W12T + 16384)
#define PK_TOTAL  (PK_WHCT + 65536)     /* 2,326,528 */

__device__ __align__(16) float  g_resbuf[2][RES_SZ];
__device__ __align__(16) float  g_skip[SKIP_SZ];
__device__ __align__(16) float  g_y2[SKIP_SZ];
__device__ __align__(16) float  g_wpack[PK_TOTAL];
__device__ double g_stats[NLAYERS*256];

/* ---------------- f32x2 packed-FMA helpers (Blackwell) ------------- */
__device__ __forceinline__ void ffma2(unsigned long long &acc,
                                      unsigned long long x,
                                      unsigned long long w) {
    asm("fma.rn.f32x2 %0, %1, %2, %0;" : "+l"(acc) : "l"(x), "l"(w));
}
__device__ __forceinline__ unsigned long long pack2(float lo, float hi) {
    unsigned long long r;
    asm("mov.b64 %0, {%1, %2};" : "=l"(r) : "f"(lo), "f"(hi));
    return r;
}
__device__ __forceinline__ float2 unpack2(unsigned long long v) {
    float lo, hi;
    asm("mov.b64 {%0, %1}, %2;" : "=f"(lo), "=f"(hi) : "l"(v));
    return make_float2(lo, hi);
}

/* ---------------- fast activations: MUFU ex2/rcp (~4 instr each) --- */
#define LOG2E  1.4426950408889634f
__device__ __forceinline__ float ex2f(float x) {
    float r; asm("ex2.approx.f32 %0, %1;" : "=f"(r) : "f"(x)); return r;
}
__device__ __forceinline__ float rcpf(float x) {
    float r; asm("rcp.approx.f32 %0, %1;" : "=f"(r) : "f"(x)); return r;
}
/* sigm(z) = 1/(1+e^-z) */
__device__ __forceinline__ float sigm(float z) {
    return rcpf(1.f + ex2f(-LOG2E * z));
}
/* tanh(z) = 1 - 2/(1+e^{2z}) */
__device__ __forceinline__ float tanh_fast(float z) {
    return fmaf(-2.f, rcpf(1.f + ex2f((2.f*LOG2E) * z)), 1.f);
}

/* ---------------- cp.async (LDGSTS): zero-register prefetch -------- */
__device__ __forceinline__ void cp_async16(uint32_t dst_smem, const float* src) {
    asm volatile("cp.async.cg.shared.global [%0], [%1], 16;" :: "r"(dst_smem), "l"(src));
}
__device__ __forceinline__ void cp_commit() {
    asm volatile("cp.async.commit_group;");
}
__device__ __forceinline__ void cp_wait0() {
    asm volatile("cp.async.wait_group 0;");
}

/* ------------------------------------------------------------------ */
/* Weight repack + stats zero (fused; both rerun per graph replay)    */
/* ------------------------------------------------------------------ */
__global__ void pack_kernel(const float* __restrict__ Wf, const float* __restrict__ Wg,
                            const float* __restrict__ W1, const float* __restrict__ W10,
                            const float* __restrict__ W11, const float* __restrict__ W12,
                            const float* __restrict__ Whc)
{
    int idx = blockIdx.x * blockDim.x + threadIdx.x;
    if (idx < NLAYERS*256) g_stats[idx] = 0.0;
    if (idx >= PK_TOTAL) return;
    float v;
    if (idx < PK_LAYERS) {
        int j = idx / PK_LAYER;
        int r = idx - j * PK_LAYER;
        if (r < 65536) {
            int k = r >> 8, m = r & 255;
            int tap = k >> 7, c = k & 127;
            if (m < 128) v = Wf[((j*128 + m)*128 + c)*2 + tap];
            else         v = Wg[((j*128 + (m-128))*128 + c)*2 + tap];
        } else {
            int rr = r - 65536;
            int c = rr >> 7, o = rr & 127;
            v = W1[(j*128 + o)*128 + c];
        }
    } else if (idx < PK_W11T) {
        int rr = idx - PK_W10T; int c = rr >> 7, o = rr & 127; v = W10[o*128 + c];
    } else if (idx < PK_W12T) {
        int rr = idx - PK_W11T; int c = rr >> 7, o = rr & 127; v = W11[o*128 + c];
    } else if (idx < PK_WHCT) {
        int rr = idx - PK_W12T; int c = rr >> 7, o = rr & 127; v = W12[o*128 + c];
    } else {
        int rr = idx - PK_WHCT;
        int k = rr >> 8, o = rr & 255;
        int tap = k >> 7, c = k & 127;
        v = Whc[(o*128 + c)*2 + tap];
    }
    g_wpack[idx] = v;
}

/* ------------------------------------------------------------------ */
/* stats helper: warp-reduce two (sum, sumsq) pairs, lane0 atomics    */
/* ------------------------------------------------------------------ */
__device__ __forceinline__ void stats_commit(int layer, int o0, int o1,
                                             float ls0, float lq0,
                                             float ls1, float lq1, int lane)
{
    #pragma unroll
    for (int off = 16; off; off >>= 1) {
        ls0 += __shfl_xor_sync(0xffffffffu, ls0, off);
        lq0 += __shfl_xor_sync(0xffffffffu, lq0, off);
        ls1 += __shfl_xor_sync(0xffffffffu, ls1, off);
        lq1 += __shfl_xor_sync(0xffffffffu, lq1, off);
    }
    if (lane == 0) {
        atomicAdd(&g_stats[layer*256 + o0],       (double)ls0);
        atomicAdd(&g_stats[layer*256 + 128 + o0], (double)lq0);
        atomicAdd(&g_stats[layer*256 + o1],       (double)ls1);
        atomicAdd(&g_stats[layer*256 + 128 + o1], (double)lq1);
    }
}

/* 1x1 GEMM inner chunk: 64 k-values from xs, pairs over out-channel   */
__device__ __forceinline__ void gemm1x1_chunk(const float* __restrict__ xsm,
                                              const float* __restrict__ wsm,
                                              unsigned long long acc[4][4],
                                              int cb, int lane, int og)
{
    #pragma unroll
    for (int cc = 0; cc < 64; cc++) {
        float4 xv = *(const float4*)(xsm + (cb+cc)*TT + lane*4);
        unsigned long long xp0 = pack2(xv.x, xv.x);
        unsigned long long xp1 = pack2(xv.y, xv.y);
        unsigned long long xp2 = pack2(xv.z, xv.z);
        unsigned long long xp3 = pack2(xv.w, xv.w);
        const ulonglong2* w2 = (const ulonglong2*)(wsm + cc*128 + og*8);
        ulonglong2 wA = w2[0], wB = w2[1];
        ffma2(acc[0][0], xp0, wA.x); ffma2(acc[0][1], xp1, wA.x);
        ffma2(acc[0][2], xp2, wA.x); ffma2(acc[0][3], xp3, wA.x);
        ffma2(acc[1][0], xp0, wA.y); ffma2(acc[1][1], xp1, wA.y);
        ffma2(acc[1][2], xp2, wA.y); ffma2(acc[1][3], xp3, wA.y);
        ffma2(acc[2][0], xp0, wB.x); ffma2(acc[2][1], xp1, wB.x);
        ffma2(acc[2][2], xp2, wB.x); ffma2(acc[2][3], xp3, wB.x);
        ffma2(acc[3][0], xp0, wB.y); ffma2(acc[3][1], xp1, wB.y);
        ffma2(acc[3][2], xp2, wB.y); ffma2(acc[3][3], xp3, wB.y);
    }
}

/* ------------------------------------------------------------------ */
/* Layer 0: in_channels = 1                                            */
/* ------------------------------------------------------------------ */
__global__ void __launch_bounds__(512,1) layer0_kernel(
    const float* __restrict__ x,  const float* __restrict__ Wf0,
    const float* __restrict__ bf0, const float* __restrict__ Wg0,
    const float* __restrict__ bg0, const float* __restrict__ b10)
{
    extern __shared__ float sm[];
    float* hs   = sm;                 /* 16384 */
    float* wsm  = sm + 16384;         /* 8192  */
    float* xs   = sm + 24576;         /* 132   */

    int b  = blockIdx.y;
    int t0 = blockIdx.x * TT;
    int tid = threadIdx.x, lane = tid & 31, og = tid >> 5;

    const float* xb = x + (size_t)b * T_LEN;
    if (tid < 129) {
        int t = t0 - 1 + tid;
        xs[tid] = (t >= 0) ? xb[t] : 0.f;
    }
    __syncthreads();

    /* gated conv, in_ch = 1, dilation 1 */
    #pragma unroll
    for (int i = 0; i < 8; i++) {
        int c = og*8 + i;
        float wfa = Wf0[c*2], wfb = Wf0[c*2+1];
        float wga = Wg0[c*2], wgb = Wg0[c*2+1];
        float bfv = bf0[c],   bgv = bg0[c];
        #pragma unroll
        for (int u = 0; u < 4; u++) {
            int tt = lane*4 + u;
            float xm = xs[tt], x0 = xs[tt+1];
            float zf = fmaf(wfa, xm, fmaf(wfb, x0, bfv));
            float zg = fmaf(wga, xm, fmaf(wgb, x0, bgv));
            hs[c*TT + tt] = tanh_fast(zf) * sigm(zg);
        }
    }
    __syncthreads();

    /* 1x1 conv */
    unsigned long long acc2[4][4];
    #pragma unroll
    for (int p = 0; p < 4; p++) {
        unsigned long long v = pack2(b10[og*8 + 2*p], b10[og*8 + 2*p + 1]);
        #pragma unroll
        for (int u = 0; u < 4; u++) acc2[p][u] = v;
    }
    const float* w1g = g_wpack + PK_W10T;
    for (int ch = 0; ch < 2; ch++) {
        #pragma unroll
        for (int r = 0; r < 4; r++) {
            int fidx = (r*512 + tid) * 4;
            *(float4*)(wsm + fidx) = *(const float4*)(w1g + ch*8192 + fidx);
        }
        __syncthreads();
        gemm1x1_chunk(hs, wsm, acc2, ch*64, lane, og);
        __syncthreads();
    }

    /* epilogue — NOTE: xs+1 is only 4B-aligned, scalar LDS only */
    float* rout = g_resbuf[0] + (size_t)b * H * T_LEN;
    float* ssb  = g_skip + (size_t)b * H * OW;
    float xr0 = xs[1 + lane*4];
    float xr1 = xs[2 + lane*4];
    float xr2 = xs[3 + lane*4];
    float xr3 = xs[4 + lane*4];
    #pragma unroll
    for (int p = 0; p < 4; p++) {
        int o0 = og*8 + 2*p, o1 = o0 + 1;
        float2 s0 = unpack2(acc2[p][0]), s1 = unpack2(acc2[p][1]);
        float2 s2 = unpack2(acc2[p][2]), s3 = unpack2(acc2[p][3]);
        float4 rv0 = make_float4(s0.x+xr0, s1.x+xr1, s2.x+xr2, s3.x+xr3);
        float4 rv1 = make_float4(s0.y+xr0, s1.y+xr1, s2.y+xr2, s3.y+xr3);
        *(float4*)(rout + (size_t)o0*T_LEN + t0 + lane*4) = rv0;
        *(float4*)(rout + (size_t)o1*T_LEN + t0 + lane*4) = rv1;
        float ls0 = rv0.x+rv0.y+rv0.z+rv0.w;
        float lq0 = rv0.x*rv0.x+rv0.y*rv0.y+rv0.z*rv0.z+rv0.w*rv0.w;
        float ls1 = rv1.x+rv1.y+rv1.z+rv1.w;
        float lq1 = rv1.x*rv1.x+rv1.y*rv1.y+rv1.z*rv1.z+rv1.w*rv1.w;
        float sk0[4] = {s0.x, s1.x, s2.x, s3.x};
        float sk1[4] = {s0.y, s1.y, s2.y, s3.y};
        #pragma unroll
        for (int u = 0; u < 4; u++) {
            int t = t0 + lane*4 + u;
            if (t >= SKIP_OFF) {
                ssb[(size_t)o0*OW + (t - SKIP_OFF)] = sk0[u];
                ssb[(size_t)o1*OW + (t - SKIP_OFF)] = sk1[u];
            }
        }
        stats_commit(0, o0, o1, ls0, lq0, ls1, lq1, lane);
    }
}

/* ------------------------------------------------------------------ */
/* Fused layer kernel (layers 1..27): per-block BN finalize, BN-folded */
/* load, gated conv (cp.async double-buffered weights), 1x1, residual */
/* ------------------------------------------------------------------ */
__global__ void __launch_bounds__(512,1) layer_kernel(
    const float* __restrict__ bfA, const float* __restrict__ bgA,
    const float* __restrict__ b1A, const float* __restrict__ gamma,
    const float* __restrict__ beta, int layer, int d)
{
    extern __shared__ float sm[];
    float* tileA = sm;
    float* tileB = sm + H*TT;
    float* wsm0  = sm + 2*H*TT;
    float* wsm1  = wsm0 + 8192;
    float* bnsc  = wsm1 + 8192;
    float* bnsh  = bnsc + 128;

    const float* resin  = g_resbuf[(layer-1) & 1];
    float*       resout = g_resbuf[layer & 1];

    int b  = blockIdx.y;
    int t0 = blockIdx.x * TT;
    int tid = threadIdx.x, lane = tid & 31, og = tid >> 5;

    uint32_t wsm0_u = (uint32_t)__cvta_generic_to_shared(wsm0);
    uint32_t wsm1_u = (uint32_t)__cvta_generic_to_shared(wsm1);

    /* per-block BN finalize from fp64 stats of previous layer */
    if (tid < H) {
        const double N = 4.0 * (double)T_LEN;
        double s = g_stats[(layer-1)*256 + tid];
        double q = g_stats[(layer-1)*256 + 128 + tid];
        double mean = s / N;
        double var  = q / N - mean*mean;
        float sc = gamma[(layer-1)*H + tid] * rsqrtf((float)var + 1e-5f);
        bnsc[tid] = sc;
        bnsh[tid] = fmaf(-(float)mean, sc, beta[(layer-1)*H + tid]);
    }
    __syncthreads();

    const float* src = resin + (size_t)b * H * T_LEN;
    const float* wbase = g_wpack + (size_t)(layer-1) * PK_LAYER;

    /* kick off chunk-0 weight stage with cp.async before tile loads */
    {
        cp_async16(wsm0_u + (0*512 + tid)*16, wbase + (0*512 + tid)*4);
        cp_async16(wsm0_u + (1*512 + tid)*16, wbase + (1*512 + tid)*4);
        cp_async16(wsm0_u + (2*512 + tid)*16, wbase + (2*512 + tid)*4);
        cp_async16(wsm0_u + (3*512 + tid)*16, wbase + (3*512 + tid)*4);
        cp_commit();
    }

    /* load normalized input tiles: tileB = x_norm(t), tileA = x_norm(t-d) */
    if ((d & 3) == 0) {
        #pragma unroll
        for (int r = 0; r < 8; r++) {
            int c = og + 16*r;
            float s = bnsc[c], tsh = bnsh[c];
            const float* row = src + (size_t)c * T_LEN;
            float4 vB = *(const float4*)(row + t0 + lane*4);
            *(float4*)(tileB + c*TT + lane*4) =
                make_float4(fmaf(s,vB.x,tsh), fmaf(s,vB.y,tsh), fmaf(s,vB.z,tsh), fmaf(s,vB.w,tsh));
            int ta = t0 - d + lane*4;
            float4 oA = make_float4(0.f,0.f,0.f,0.f);
            if (ta >= 0) {
                float4 vA = *(const float4*)(row + ta);
                oA = make_float4(fmaf(s,vA.x,tsh), fmaf(s,vA.y,tsh), fmaf(s,vA.z,tsh), fmaf(s,vA.w,tsh));
            }
            *(float4*)(tileA + c*TT + lane*4) = oA;
        }
    } else {
        #pragma unroll
        for (int r = 0; r < 8; r++) {
            int c = og + 16*r;
            float s = bnsc[c], tsh = bnsh[c];
            const float* row = src + (size_t)c * T_LEN;
            float4 vB = *(const float4*)(row + t0 + lane*4);
            *(float4*)(tileB + c*TT + lane*4) =
                make_float4(fmaf(s,vB.x,tsh), fmaf(s,vB.y,tsh), fmaf(s,vB.z,tsh), fmaf(s,vB.w,tsh));
            #pragma unroll
            for (int u = 0; u < 4; u++) {
                int ta = t0 - d + lane*4 + u;
                tileA[c*TT + lane*4 + u] = (ta >= 0) ? fmaf(s, row[ta], tsh) : 0.f;
            }
        }
    }

    /* gated conv: M=256 (f||g), K=256 (tap0=tileA, tap1=tileB).
       Weights double-buffered via cp.async. */
    unsigned long long accf[4][4], accg[4][4];
    {
        const float* bfL = bfA + (layer-1)*H;
        const float* bgL = bgA + (layer-1)*H;
        #pragma unroll
        for (int p = 0; p < 4; p++) {
            unsigned long long vf = pack2(bfL[og*8+2*p], bfL[og*8+2*p+1]);
            unsigned long long vg = pack2(bgL[og*8+2*p], bgL[og*8+2*p+1]);
            #pragma unroll
            for (int u = 0; u < 4; u++) { accf[p][u] = vf; accg[p][u] = vg; }
        }
    }
    cp_wait0();
    __syncthreads();   /* covers tiles + bn + wsm0 */

    int cur = 0;
    for (int ch = 0; ch < 8; ch++) {
        if (ch < 7) {
            const float* wgp = wbase + (ch+1) * (KC*256);
            uint32_t wn = cur ? wsm0_u : wsm1_u;
            cp_async16(wn + (0*512 + tid)*16, wgp + (0*512 + tid)*4);
            cp_async16(wn + (1*512 + tid)*16, wgp + (1*512 + tid)*4);
            cp_async16(wn + (2*512 + tid)*16, wgp + (2*512 + tid)*4);
            cp_async16(wn + (3*512 + tid)*16, wgp + (3*512 + tid)*4);
            cp_commit();
        }
        const float* wcur = cur ? wsm1 : wsm0;
        const float* xsrc = ((ch < 4) ? tileA : tileB) + ((ch & 3) * KC) * TT;
        #pragma unroll
        for (int kk = 0; kk < KC; kk++) {
            float4 xv = *(const float4*)(xsrc + kk*TT + lane*4);
            unsigned long long xp0 = pack2(xv.x, xv.x);
            unsigned long long xp1 = pack2(xv.y, xv.y);
            unsigned long long xp2 = pack2(xv.z, xv.z);
            unsigned long long xp3 = pack2(xv.w, xv.w);
            const ulonglong2* wf2 = (const ulonglong2*)(wcur + kk*256 + og*8);
            const ulonglong2* wg2 = (const ulonglong2*)(wcur + kk*256 + 128 + og*8);
            ulonglong2 wfA = wf2[0], wfB = wf2[1];
            ulonglong2 wgA = wg2[0], wgB = wg2[1];
            ffma2(accf[0][0], xp0, wfA.x); ffma2(accf[0][1], xp1, wfA.x);
            ffma2(accf[0][2], xp2, wfA.x); ffma2(accf[0][3], xp3, wfA.x);
            ffma2(accf[1][0], xp0, wfA.y); ffma2(accf[1][1], xp1, wfA.y);
            ffma2(accf[1][2], xp2, wfA.y); ffma2(accf[1][3], xp3, wfA.y);
            ffma2(accf[2][0], xp0, wfB.x); ffma2(accf[2][1], xp1, wfB.x);
            ffma2(accf[2][2], xp2, wfB.x); ffma2(accf[2][3], xp3, wfB.x);
            ffma2(accf[3][0], xp0, wfB.y); ffma2(accf[3][1], xp1, wfB.y);
            ffma2(accf[3][2], xp2, wfB.y); ffma2(accf[3][3], xp3, wfB.y);
            ffma2(accg[0][0], xp0, wgA.x); ffma2(accg[0][1], xp1, wgA.x);
            ffma2(accg[0][2], xp2, wgA.x); ffma2(accg[0][3], xp3, wgA.x);
            ffma2(accg[1][0], xp0, wgA.y); ffma2(accg[1][1], xp1, wgA.y);
            ffma2(accg[1][2], xp2, wgA.y); ffma2(accg[1][3], xp3, wgA.y);
            ffma2(accg[2][0], xp0, wgB.x); ffma2(accg[2][1], xp1, wgB.x);
            ffma2(accg[2][2], xp2, wgB.x); ffma2(accg[2][3], xp3, wgB.x);
            ffma2(accg[3][0], xp0, wgB.y); ffma2(accg[3][1], xp1, wgB.y);
            ffma2(accg[3][2], xp2, wgB.y); ffma2(accg[3][3], xp3, wgB.y);
        }
        if (ch < 7) { cp_wait0(); cur ^= 1; }
        __syncthreads();
    }

    /* gating -> hs (reuse tileA) */
    float* hs = tileA;
    #pragma unroll
    for (int p = 0; p < 4; p++) {
        float2 f0 = unpack2(accf[p][0]), f1 = unpack2(accf[p][1]);
        float2 f2 = unpack2(accf[p][2]), f3 = unpack2(accf[p][3]);
        float2 g0 = unpack2(accg[p][0]), g1 = unpack2(accg[p][1]);
        float2 g2 = unpack2(accg[p][2]), g3 = unpack2(accg[p][3]);
        float4 h0 = make_float4(tanh_fast(f0.x)*sigm(g0.x), tanh_fast(f1.x)*sigm(g1.x),
                                tanh_fast(f2.x)*sigm(g2.x), tanh_fast(f3.x)*sigm(g3.x));
        float4 h1 = make_float4(tanh_fast(f0.y)*sigm(g0.y), tanh_fast(f1.y)*sigm(g1.y),
                                tanh_fast(f2.y)*sigm(g2.y), tanh_fast(f3.y)*sigm(g3.y));
        *(float4*)(hs + (og*8+2*p)*TT + lane*4)   = h0;
        *(float4*)(hs + (og*8+2*p+1)*TT + lane*4) = h1;
    }

    /* 1x1 conv: chunk0 staged to wsm0 + chunk1 via cp.async to wsm1 */
    unsigned long long acc2[4][4];
    {
        const float* b1L = b1A + (layer-1)*H;
        #pragma unroll
        for (int p = 0; p < 4; p++) {
            unsigned long long v = pack2(b1L[og*8+2*p], b1L[og*8+2*p+1]);
            #pragma unroll
            for (int u = 0; u < 4; u++) acc2[p][u] = v;
        }
    }
    const float* w1g = wbase + 65536;
    cp_async16(wsm0_u + (0*512 + tid)*16, w1g + (0*512 + tid)*4);
    cp_async16(wsm0_u + (1*512 + tid)*16, w1g + (1*512 + tid)*4);
    cp_async16(wsm0_u + (2*512 + tid)*16, w1g + (2*512 + tid)*4);
    cp_async16(wsm0_u + (3*512 + tid)*16, w1g + (3*512 + tid)*4);
    cp_commit();
    cp_async16(wsm1_u + (0*512 + tid)*16, w1g + 8192 + (0*512 + tid)*4);
    cp_async16(wsm1_u + (1*512 + tid)*16, w1g + 8192 + (1*512 + tid)*4);
    cp_async16(wsm1_u + (2*512 + tid)*16, w1g + 8192 + (2*512 + tid)*4);
    cp_async16(wsm1_u + (3*512 + tid)*16, w1g + 8192 + (3*512 + tid)*4);
    cp_commit();
    asm volatile("cp.async.wait_group 1;");   /* wsm0 landed */
    __syncthreads();   /* hs + wsm0 ready */
    gemm1x1_chunk(hs, wsm0, acc2, 0, lane, og);
    cp_wait0();                               /* wsm1 landed */
    __syncthreads();
    gemm1x1_chunk(hs, wsm1, acc2, 64, lane, og);

    /* epilogue: residual, store, BN stats, skip accumulate
       (reads only tileB, untouched since input load) */
    float* rout = resout + (size_t)b * H * T_LEN;
    float* ssb  = g_skip + (size_t)b * H * OW;
    #pragma unroll
    for (int p = 0; p < 4; p++) {
        int o0 = og*8 + 2*p, o1 = o0 + 1;
        float2 s0 = unpack2(acc2[p][0]), s1 = unpack2(acc2[p][1]);
        float2 s2 = unpack2(acc2[p][2]), s3 = unpack2(acc2[p][3]);
        float4 xB0 = *(const float4*)(tileB + o0*TT + lane*4);
        float4 xB1 = *(const float4*)(tileB + o1*TT + lane*4);
        float4 rv0 = make_float4(s0.x+xB0.x, s1.x+xB0.y, s2.x+xB0.z, s3.x+xB0.w);
        float4 rv1 = make_float4(s0.y+xB1.x, s1.y+xB1.y, s2.y+xB1.z, s3.y+xB1.w);
        *(float4*)(rout + (size_t)o0*T_LEN + t0 + lane*4) = rv0;
        *(float4*)(rout + (size_t)o1*T_LEN + t0 + lane*4) = rv1;
        float ls0 = rv0.x+rv0.y+rv0.z+rv0.w;
        float lq0 = rv0.x*rv0.x+rv0.y*rv0.y+rv0.z*rv0.z+rv0.w*rv0.w;
        float ls1 = rv1.x+rv1.y+rv1.z+rv1.w;
        float lq1 = rv1.x*rv1.x+rv1.y*rv1.y+rv1.z*rv1.z+rv1.w*rv1.w;
        float sk0[4] = {s0.x, s1.x, s2.x, s3.x};
        float sk1[4] = {s0.y, s1.y, s2.y, s3.y};
        #pragma unroll
        for (int u = 0; u < 4; u++) {
            int t = t0 + lane*4 + u;
            if (t >= SKIP_OFF) {
                ssb[(size_t)o0*OW + (t - SKIP_OFF)] += sk0[u];
                ssb[(size_t)o1*OW + (t - SKIP_OFF)] += sk1[u];
            }
        }
        stats_commit(layer, o0, o1, ls0, lq0, ls1, lq1, lane);
    }
}

/* ------------------------------------------------------------------ */
/* Head part 1: y2 = relu(W12 @ relu(W11 @ skip_sum + b11) + b12)     */
/* ------------------------------------------------------------------ */
__global__ void __launch_bounds__(512,1) head1_kernel(
    const float* __restrict__ b11, const float* __restrict__ b12)
{
    extern __shared__ float sm[];
    float* xs  = sm;
    float* ys  = sm + 16384;
    float* wsm = sm + 32768;

    int b  = blockIdx.y;
    int t0 = blockIdx.x * TT;
    int tid = threadIdx.x, lane = tid & 31, og = tid >> 5;

    const float* sk = g_skip + (size_t)b * H * OW;
    #pragma unroll
    for (int r = 0; r < 32; r++) {
        int id = r*512 + tid;
        int c = id >> 7, tt = id & 127;
        int t = t0 + tt;
        xs[c*TT + tt] = (t < OW) ? sk[(size_t)c*OW + t] : 0.f;
    }
    __syncthreads();

    unsigned long long acc[4][4];
    #pragma unroll
    for (int p = 0; p < 4; p++) {
        unsigned long long v = pack2(b11[og*8+2*p], b11[og*8+2*p+1]);
        #pragma unroll
        for (int u = 0; u < 4; u++) acc[p][u] = v;
    }
    for (int ch = 0; ch < 2; ch++) {
        #pragma unroll
        for (int r = 0; r < 4; r++) {
            int fidx = (r*512 + tid) * 4;
            *(float4*)(wsm + fidx) = *(const float4*)(g_wpack + PK_W11T + ch*8192 + fidx);
        }
        __syncthreads();
        gemm1x1_chunk(xs, wsm, acc, ch*64, lane, og);
        __syncthreads();
    }
    #pragma unroll
    for (int p = 0; p < 4; p++) {
        float2 v0 = unpack2(acc[p][0]), v1 = unpack2(acc[p][1]);
        float2 v2 = unpack2(acc[p][2]), v3 = unpack2(acc[p][3]);
        *(float4*)(ys + (og*8+2*p)*TT + lane*4) =
            make_float4(fmaxf(v0.x,0.f), fmaxf(v1.x,0.f), fmaxf(v2.x,0.f), fmaxf(v3.x,0.f));
        *(float4*)(ys + (og*8+2*p+1)*TT + lane*4) =
            make_float4(fmaxf(v0.y,0.f), fmaxf(v1.y,0.f), fmaxf(v2.y,0.f), fmaxf(v3.y,0.f));
    }
    __syncthreads();

    /* second 1x1 + relu -> g_y2 */
    #pragma unroll
    for (int p = 0; p < 4; p++) {
        unsigned long long v = pack2(b12[og*8+2*p], b12[og*8+2*p+1]);
        #pragma unroll
        for (int u = 0; u < 4; u++) acc[p][u] = v;
    }
    for (int ch = 0; ch < 2; ch++) {
        #pragma unroll
        for (int r = 0; r < 4; r++) {
            int fidx = (r*512 + tid) * 4;
            *(float4*)(wsm + fidx) = *(const float4*)(g_wpack + PK_W12T + ch*8192 + fidx);
        }
        __syncthreads();
        gemm1x1_chunk(ys, wsm, acc, ch*64, lane, og);
        __syncthreads();
    }
    float* y2 = g_y2 + (size_t)b * H * OW;
    #pragma unroll
    for (int p = 0; p < 4; p++) {
        float2 v0 = unpack2(acc[p][0]), v1 = unpack2(acc[p][1]);
        float2 v2 = unpack2(acc[p][2]), v3 = unpack2(acc[p][3]);
        float a0[4] = {v0.x, v1.x, v2.x, v3.x};
        float a1[4] = {v0.y, v1.y, v2.y, v3.y};
        #pragma unroll
        for (int u = 0; u < 4; u++) {
            int t = t0 + lane*4 + u;
            if (t < OW) {
                y2[(size_t)(og*8+2*p)*OW + t]   = fmaxf(a0[u], 0.f);
                y2[(size_t)(og*8+2*p+1)*OW + t] = fmaxf(a1[u], 0.f);
            }
        }
    }
}

/* ------------------------------------------------------------------ */
/* Head part 2: final conv1d (K=2, no pad) -> out [4,256,16385]       */
/* ------------------------------------------------------------------ */
__global__ void __launch_bounds__(512,1) head2_kernel(
    const float* __restrict__ bhc, float* __restrict__ out)
{
    extern __shared__ float sm[];
    float* tileA = sm;            /* y2(t)   */
    float* tileB = sm + 16384;    /* y2(t+1) */
    float* wsm   = sm + 32768;

    int b  = blockIdx.y;
    int t0 = blockIdx.x * TT;
    int tid = threadIdx.x, lane = tid & 31, og = tid >> 5;

    const float* y2 = g_y2 + (size_t)b * H * OW;
    #pragma unroll
    for (int r = 0; r < 32; r++) {
        int id = r*512 + tid;
        int c = id >> 7, tt = id & 127;
        int t  = t0 + tt;
        int t2 = t0 + tt + 1;
        tileA[c*TT + tt] = (t  < OW) ? y2[(size_t)c*OW + t]  : 0.f;
        tileB[c*TT + tt] = (t2 < OW) ? y2[(size_t)c*OW + t2] : 0.f;
    }
    __syncthreads();

    unsigned long long acca[4][4], accb[4][4];
    #pragma unroll
    for (int p = 0; p < 4; p++) {
        unsigned long long va = pack2(bhc[og*8+2*p],       bhc[og*8+2*p+1]);
        unsigned long long vb = pack2(bhc[128+og*8+2*p],   bhc[128+og*8+2*p+1]);
        #pragma unroll
        for (int u = 0; u < 4; u++) { acca[p][u] = va; accb[p][u] = vb; }
    }
    for (int ch = 0; ch < 8; ch++) {
        #pragma unroll
        for (int r = 0; r < 4; r++) {
            int fidx = (r*512 + tid) * 4;
            *(float4*)(wsm + fidx) = *(const float4*)(g_wpack + PK_WHCT + ch*(KC*256) + fidx);
        }
        __syncthreads();
        const float* xsrc = ((ch < 4) ? tileA : tileB) + ((ch & 3) * KC) * TT;
        #pragma unroll
        for (int kk = 0; kk < KC; kk++) {
            float4 xv = *(const float4*)(xsrc + kk*TT + lane*4);
            unsigned long long xp0 = pack2(xv.x, xv.x);
            unsigned long long xp1 = pack2(xv.y, xv.y);
            unsigned long long xp2 = pack2(xv.z, xv.z);
            unsigned long long xp3 = pack2(xv.w, xv.w);
            const ulonglong2* wa2 = (const ulonglong2*)(wsm + kk*256 + og*8);
            const ulonglong2* wb2 = (const ulonglong2*)(wsm + kk*256 + 128 + og*8);
            ulonglong2 waA = wa2[0], waB = wa2[1];
            ulonglong2 wbA = wb2[0], wbB = wb2[1];
            ffma2(acca[0][0], xp0, waA.x); ffma2(acca[0][1], xp1, waA.x);
            ffma2(acca[0][2], xp2, waA.x); ffma2(acca[0][3], xp3, waA.x);
            ffma2(acca[1][0], xp0, waA.y); ffma2(acca[1][1], xp1, waA.y);
            ffma2(acca[1][2], xp2, waA.y); ffma2(acca[1][3], xp3, waA.y);
            ffma2(acca[2][0], xp0, waB.x); ffma2(acca[2][1], xp1, waB.x);
            ffma2(acca[2][2], xp2, waB.x); ffma2(acca[2][3], xp3, waB.x);
            ffma2(acca[3][0], xp0, waB.y); ffma2(acca[3][1], xp1, waB.y);
            ffma2(acca[3][2], xp2, waB.y); ffma2(acca[3][3], xp3, waB.y);
            ffma2(accb[0][0], xp0, wbA.x); ffma2(accb[0][1], xp1, wbA.x);
            ffma2(accb[0][2], xp2, wbA.x); ffma2(accb[0][3], xp3, wbA.x);
            ffma2(accb[1][0], xp0, wbA.y); ffma2(accb[1][1], xp1, wbA.y);
            ffma2(accb[1][2], xp2, wbA.y); ffma2(accb[1][3], xp3, wbA.y);
            ffma2(accb[2][0], xp0, wbB.x); ffma2(accb[2][1], xp1, wbB.x);
            ffma2(accb[2][2], xp2, wbB.x); ffma2(accb[2][3], xp3, wbB.x);
            ffma2(accb[3][0], xp0, wbB.y); ffma2(accb[3][1], xp1, wbB.y);
            ffma2(accb[3][2], xp2, wbB.y); ffma2(accb[3][3], xp3, wbB.y);
        }
        __syncthreads();
    }

    const int NOUT = OW - 1;   /* 16385 */
    float* ob = out + (size_t)b * NCLS * NOUT;
    #pragma unroll
    for (int p = 0; p < 4; p++) {
        float2 a0 = unpack2(acca[p][0]), a1 = unpack2(acca[p][1]);
        float2 a2 = unpack2(acca[p][2]), a3 = unpack2(acca[p][3]);
        float2 b0 = unpack2(accb[p][0]), b1 = unpack2(accb[p][1]);
        float2 b2 = unpack2(accb[p][2]), b3 = unpack2(accb[p][3]);
        float va0[4] = {a0.x, a1.x, a2.x, a3.x};
        float va1[4] = {a0.y, a1.y, a2.y, a3.y};
        float vb0[4] = {b0.x, b1.x, b2.x, b3.x};
        float vb1[4] = {b0.y, b1.y, b2.y, b3.y};
        #pragma unroll
        for (int u = 0; u < 4; u++) {
            int t = t0 + lane*4 + u;
            if (t < NOUT) {
                ob[(size_t)(og*8+2*p)*NOUT + t]       = va0[u];
                ob[(size_t)(og*8+2*p+1)*NOUT + t]     = va1[u];
                ob[(size_t)(128+og*8+2*p)*NOUT + t]   = vb0[u];
                ob[(size_t)(128+og*8+2*p+1)*NOUT + t] = vb1[u];
            }
        }
    }
}

/* ------------------------------------------------------------------ */
extern "C" void kernel_launch(void* const* d_in, const int* in_sizes, int n_in,
                              void* d_out, int out_size)
{
    const float* x    = (const float*)d_in[0];
    const float* Wf0  = (const float*)d_in[1];
    const float* bf0  = (const float*)d_in[2];
    const float* Wg0  = (const float*)d_in[3];
    const float* bg0  = (const float*)d_in[4];
    const float* W10  = (const float*)d_in[5];
    const float* b10  = (const float*)d_in[6];
    const float* Wf   = (const float*)d_in[7];
    const float* bfA  = (const float*)d_in[8];
    const float* Wg   = (const float*)d_in[9];
    const float* bgA  = (const float*)d_in[10];
    const float* W1   = (const float*)d_in[11];
    const float* b1A  = (const float*)d_in[12];
    const float* gamma= (const float*)d_in[13];
    const float* beta = (const float*)d_in[14];
    const float* W11  = (const float*)d_in[15];
    const float* b11  = (const float*)d_in[16];
    const float* W12  = (const float*)d_in[17];
    const float* b12  = (const float*)d_in[18];
    const float* Whc  = (const float*)d_in[19];
    const float* bhc  = (const float*)d_in[20];
    float* out = (float*)d_out;

    const int SMEM_L0    = (16384 + 8192 + 132) * 4;            /*  98,832 B */
    const int SMEM_LAYER = (2*16384 + 2*8192 + 256) * 4;        /* 197,632 B */
    const int SMEM_HEAD  = (16384 + 16384 + 8192) * 4;          /* 163,840 B */

    cudaFuncSetAttribute(layer0_kernel, cudaFuncAttributeMaxDynamicSharedMemorySize, SMEM_L0);
    cudaFuncSetAttribute(layer_kernel,  cudaFuncAttributeMaxDynamicSharedMemorySize, SMEM_LAYER);
    cudaFuncSetAttribute(head1_kernel,  cudaFuncAttributeMaxDynamicSharedMemorySize, SMEM_HEAD);
    cudaFuncSetAttribute(head2_kernel,  cudaFuncAttributeMaxDynamicSharedMemorySize, SMEM_HEAD);

    pack_kernel<<<(PK_TOTAL + 511)/512, 512>>>(Wf, Wg, W1, W10, W11, W12, Whc);

    dim3 grid(T_LEN / TT, 4);           /* (384, 4) */
    layer0_kernel<<<grid, 512, SMEM_L0>>>(x, Wf0, bf0, Wg0, bg0, b10);

    for (int i = 1; i < NLAYERS; i++) {
        int d = 1 << (i % 14);
        layer_kernel<<<grid, 512, SMEM_LAYER>>>(bfA, bgA, b1A, gamma, beta, i, d);
    }

    dim3 hgrid((OW + TT - 1) / TT, 4);  /* (129, 4) */
    head1_kernel<<<hgrid, 512, SMEM_HEAD>>>(b11, b12);
    head2_kernel<<<hgrid, 512, SMEM_HEAD>>>(bhc, out);
}